// round 14
// baseline (speedup 1.0000x reference)
#include <cuda_runtime.h>
#include <cuda_bf16.h>
#include <math.h>
#include <stdint.h>

// Problem constants (fixed by the dataset)
#define BB  2
#define LL  8192
#define DD  1024
#define HH  16
#define PP  64
#define CLc 256
#define NCC 32
#define MM  (BB*LL)   // 16384 rows

#if defined(__CUDA_ARCH_FEAT_SM103_ALL) || defined(__CUDA_ARCH_FEAT_SM100_ALL) || \
    defined(__CUDA_ARCH_FEAT_SM101_ALL) || defined(__CUDA_ARCH_SPECIFIC__)
#define HAS_TCGEN05 1
#else
#define HAS_TCGEN05 0
#endif

#define WSZB ((size_t)2 * DD * DD)   // bytes per bf16 weight matrix

// ---------------------------------------------------------------------------
// Scratch
// ---------------------------------------------------------------------------
__device__ float g_x[BB*LL*DD];     // PRE-SCALED x*dt (fp32)
__device__ float g_dt[BB*LL*HH];
__device__ float g_ac[BB*LL*HH];
__device__ float g_cdec[BB*NCC*HH];
__device__ float g_states[BB*NCC*HH*PP*PP];
__device__ float g_prev[BB*NCC*HH*PP*PP];

// c and b as per-(rowblock,head) 16KB swizzled bf16 tiles:
//   tile = (row>>7)*HH + h ; byte off = tile*16384 + swz((row&127)*128 + p*2)
__device__ __align__(1024) __nv_bfloat16 g_tc_hi[MM*DD];
__device__ __align__(1024) __nv_bfloat16 g_tc_lo[MM*DD];
__device__ __align__(1024) __nv_bfloat16 g_tb_hi[MM*DD];
__device__ __align__(1024) __nv_bfloat16 g_tb_lo[MM*DD];

// TILED bf16 GEMM operands
__device__ __align__(1024) __nv_bfloat16 g_ahi[MM*DD];
__device__ __align__(1024) __nv_bfloat16 g_alo[MM*DD];
__device__ __align__(1024) __nv_bfloat16 g_wt_hi[4][DD*DD];
__device__ __align__(1024) __nv_bfloat16 g_wt_lo[4][DD*DD];

// ---------------------------------------------------------------------------
// Helpers
// ---------------------------------------------------------------------------
__device__ __forceinline__ uint32_t smem_u32(const void* p) {
    uint32_t a;
    asm("{ .reg .u64 t; cvta.to.shared.u64 t, %1; cvt.u32.u64 %0, t; }"
        : "=r"(a) : "l"(p));
    return a;
}
__device__ __forceinline__ uint32_t swz(uint32_t off) { return off ^ ((off >> 3) & 0x70); }

__device__ __forceinline__ void split2(float v, float& hi, float& lo) {
    __nv_bfloat16 h = __float2bfloat16(v);
    hi = __bfloat162float(h);
    lo = v - hi;
}
__device__ __forceinline__ void split_pack2(float v0, float v1,
                                            uint32_t& hi2, uint32_t& lo2) {
    asm("cvt.rn.bf16x2.f32 %0, %1, %2;" : "=r"(hi2) : "f"(v1), "f"(v0));
    float h0 = __uint_as_float(hi2 << 16);
    float h1 = __uint_as_float(hi2 & 0xFFFF0000u);
    asm("cvt.rn.bf16x2.f32 %0, %1, %2;" : "=r"(lo2) : "f"(v1 - h1), "f"(v0 - h0));
}
__device__ __forceinline__ float2 unsplit2(uint32_t hv, uint32_t lv) {
    float a = __uint_as_float(hv << 16) + __uint_as_float(lv << 16);
    float b = __uint_as_float(hv & 0xFFFF0000u) + __uint_as_float(lv & 0xFFFF0000u);
    return make_float2(a, b);
}
__device__ __forceinline__ size_t cb_off(int row, int h, int p) {
    size_t tile = (size_t)((row >> 7) * HH + h);
    return (tile << 14) + swz(((uint32_t)(row & 127) << 7) + ((uint32_t)p << 1));
}
__device__ __forceinline__ float ld_cb(const char* hi, const char* lo, int row, int h, int p) {
    size_t o = cb_off(row, h, p);
    return __bfloat162float(*(const __nv_bfloat16*)(hi + o)) +
           __bfloat162float(*(const __nv_bfloat16*)(lo + o));
}
__device__ __forceinline__ uint32_t a_tile_off(int row, int k) {
    uint32_t tile = (uint32_t)(row >> 7) * 16u + (uint32_t)(k >> 6);
    return (tile << 14) + swz(((uint32_t)(row & 127) << 7) + ((uint32_t)(k & 63) << 1));
}
__device__ __forceinline__ uint32_t b_tile_off(int n, int k) {
    uint32_t tile = (uint32_t)(n >> 8) * 16u + (uint32_t)(k >> 6);
    return (tile << 15) + swz(((uint32_t)(n & 255) << 7) + ((uint32_t)(k & 63) << 1));
}

#if HAS_TCGEN05
__device__ __forceinline__ uint32_t elect_one() {
    uint32_t pred;
    asm volatile("{\n\t.reg .pred p;\n\telect.sync _|p, 0xFFFFFFFF;\n\t"
                 "selp.b32 %0, 1, 0, p;\n\t}" : "=r"(pred));
    return pred;
}
#define MBAR_INIT(a, c) \
    asm volatile("mbarrier.init.shared.b64 [%0], %1;" :: "r"(a), "r"(c) : "memory")
#define MBAR_EXPECT_TX(a, n) \
    asm volatile("mbarrier.arrive.expect_tx.shared.b64 _, [%0], %1;" :: "r"(a), "r"(n) : "memory")
#define MBAR_WAIT(a, ph) do { \
    asm volatile("{\n\t.reg .pred P1;\n\t" \
        "WL_%=:\n\t" \
        "mbarrier.try_wait.parity.acquire.cta.shared::cta.b64 P1, [%0], %1, 0x989680;\n\t" \
        "@P1 bra.uni WD_%=;\n\tbra.uni WL_%=;\n\tWD_%=:\n\t}" \
        :: "r"(a), "r"(ph) : "memory"); \
} while (0)
#define BULK_G2S(dst, src, n, mbar) \
    asm volatile("cp.async.bulk.shared::cta.global.mbarrier::complete_tx::bytes " \
                 "[%0], [%1], %2, [%3];" \
                 :: "r"(dst), "l"(src), "r"(n), "r"(mbar) : "memory")
#define TC_ALLOC(sa, n) \
    asm volatile("tcgen05.alloc.cta_group::1.sync.aligned.shared::cta.b32 [%0], %1;" \
                 :: "r"(sa), "r"(n) : "memory")
#define TC_DEALLOC(t, n) \
    asm volatile("tcgen05.dealloc.cta_group::1.sync.aligned.b32 %0, %1;" :: "r"(t), "r"(n))
#define TC_COMMIT(a) \
    asm volatile("tcgen05.commit.cta_group::1.mbarrier::arrive::one.shared::cluster.b64 [%0];" \
                 :: "r"(a) : "memory")
#define TC_FENCE_AFTER() asm volatile("tcgen05.fence::after_thread_sync;" ::: "memory")
#define TC_FENCE_BEFORE() asm volatile("tcgen05.fence::before_thread_sync;" ::: "memory")
#define TC_WAIT_LD() asm volatile("tcgen05.wait::ld.sync.aligned;" ::: "memory")
#define FENCE_ASYNC() asm volatile("fence.proxy.async.shared::cta;" ::: "memory")

__device__ __forceinline__ void mma_f16_ss(uint32_t d, uint64_t ad, uint64_t bd,
                                           uint32_t idesc, uint32_t en) {
    asm volatile("{\n\t.reg .pred p;\n\tsetp.ne.u32 p, %4, 0;\n\t"
                 "tcgen05.mma.cta_group::1.kind::f16 [%0], %1, %2, %3, {%5,%5,%5,%5}, p;\n\t}"
                 :: "r"(d), "l"(ad), "l"(bd), "r"(idesc), "r"(en), "r"(0u) : "memory");
}
__device__ __forceinline__ void ldtm32(uint32_t* r, uint32_t ta) {
    asm volatile("tcgen05.ld.sync.aligned.32x32b.x32.b32 "
        "{%0,%1,%2,%3,%4,%5,%6,%7,%8,%9,%10,%11,%12,%13,%14,%15,"
        "%16,%17,%18,%19,%20,%21,%22,%23,%24,%25,%26,%27,%28,%29,%30,%31}, [%32];"
        : "=r"(r[0]),"=r"(r[1]),"=r"(r[2]),"=r"(r[3]),"=r"(r[4]),"=r"(r[5]),"=r"(r[6]),"=r"(r[7]),
          "=r"(r[8]),"=r"(r[9]),"=r"(r[10]),"=r"(r[11]),"=r"(r[12]),"=r"(r[13]),"=r"(r[14]),"=r"(r[15]),
          "=r"(r[16]),"=r"(r[17]),"=r"(r[18]),"=r"(r[19]),"=r"(r[20]),"=r"(r[21]),"=r"(r[22]),"=r"(r[23]),
          "=r"(r[24]),"=r"(r[25]),"=r"(r[26]),"=r"(r[27]),"=r"(r[28]),"=r"(r[29]),"=r"(r[30]),"=r"(r[31])
        : "r"(ta));
}
static constexpr uint64_t DESC_BASE =
    (uint64_t(2) << 61) | (uint64_t(1) << 46) | (uint64_t(64) << 32) | (uint64_t(1) << 16);
__device__ __forceinline__ uint64_t mk_desc(uint32_t addr) {
    return DESC_BASE | ((uint64_t)(addr >> 4) & 0x3FFF);
}
#define IDESC_N(N) ((1u<<4)|(1u<<7)|(1u<<10)|(((N)/8u)<<17)|(8u<<24))
#endif  // HAS_TCGEN05

// ---------------------------------------------------------------------------
// prep: fsplit (blocks [0,8192)) + wsplit x4 ([8192,12288)) + dt2 ([12288,12800))
// ---------------------------------------------------------------------------
#define PREP_FS 8192
#define PREP_WS 4096
#define PREP_DT 512

__global__ __launch_bounds__(256) void prep(
        const float* __restrict__ hs,
        const float* __restrict__ Wc, const float* __restrict__ Wb,
        const float* __restrict__ Wx, const float* __restrict__ Wout,
        const float* __restrict__ Wdt,
        char* __restrict__ ahi, char* __restrict__ alo,
        char* __restrict__ whi, char* __restrict__ wlo) {
    extern __shared__ float sw[];
    int bid = blockIdx.x, tid = threadIdx.x;

    if (bid < PREP_FS) {
        int t = bid * 256 + tid;
        int row = t >> 7;
        int k8 = t & 127;
        const float4* p = (const float4*)(hs + ((size_t)row << 10) + (k8 << 3));
        float4 v0 = p[0], v1 = p[1];
        uint4 hv, lv;
        split_pack2(v0.x, v0.y, hv.x, lv.x);
        split_pack2(v0.z, v0.w, hv.y, lv.y);
        split_pack2(v1.x, v1.y, hv.z, lv.z);
        split_pack2(v1.z, v1.w, hv.w, lv.w);
        uint32_t tile = (uint32_t)(row >> 7) * 16u + (uint32_t)(k8 >> 3);
        uint32_t off = (tile << 14) + swz(((uint32_t)(row & 127) << 7) + ((uint32_t)(k8 & 7) << 4));
        *(uint4*)(ahi + off) = hv;
        *(uint4*)(alo + off) = lv;
    } else if (bid < PREP_FS + PREP_WS) {
        int q = bid - PREP_FS;
        int m = q >> 10;
        const float* W = (m == 0) ? Wc : (m == 1) ? Wb : (m == 2) ? Wx : Wout;
        char* Thi = whi + (size_t)m * WSZB;
        char* Tlo = wlo + (size_t)m * WSZB;
        int qq = q & 1023;
        int bx = (qq & 31) * 32, by = (qq >> 5) * 32;
        float (*t)[33] = (float(*)[33])sw;
        int x = tid & 31, y = tid >> 5;
#pragma unroll
        for (int j = 0; j < 4; j++)
            t[y + j*8][x] = W[(size_t)(by + y + j*8) * DD + bx + x];
        __syncthreads();
#pragma unroll
        for (int j = 0; j < 4; j++) {
            float v = t[x][y + j*8];
            float h, l;
            split2(v, h, l);
            int n = bx + y + j*8, k = by + x;
            uint32_t off = b_tile_off(n, k);
            *(__nv_bfloat16*)(Thi + off) = __float2bfloat16(h);
            *(__nv_bfloat16*)(Tlo + off) = __float2bfloat16(l);
        }
    } else {
        int blk = bid - PREP_FS - PREP_WS;
        for (int i = tid; i < 16384; i += 256)
            sw[(i & 15) * 1028 + (i >> 4)] = Wdt[i];
        __syncthreads();
        int w = tid >> 5, l = tid & 31;
        int row0 = blk * 32 + w * 4;
        float acc[4][16];
#pragma unroll
        for (int r = 0; r < 4; r++)
#pragma unroll
            for (int n = 0; n < 16; n++) acc[r][n] = 0.f;
#pragma unroll
        for (int it = 0; it < 8; it++) {
            int k0 = it * 128 + l * 4;
            float4 h[4];
#pragma unroll
            for (int r = 0; r < 4; r++)
                h[r] = *(const float4*)&hs[(size_t)(row0 + r) * DD + k0];
#pragma unroll
            for (int n = 0; n < 16; n++) {
                float4 wv = *(const float4*)&sw[n * 1028 + k0];
#pragma unroll
                for (int r = 0; r < 4; r++)
                    acc[r][n] += h[r].x*wv.x + h[r].y*wv.y + h[r].z*wv.z + h[r].w*wv.w;
            }
        }
#pragma unroll
        for (int off = 16; off; off >>= 1)
#pragma unroll
            for (int r = 0; r < 4; r++)
#pragma unroll
                for (int n = 0; n < 16; n++)
                    acc[r][n] += __shfl_xor_sync(0xFFFFFFFFu, acc[r][n], off);
        if (l == 0) {
#pragma unroll
            for (int r = 0; r < 4; r++)
#pragma unroll
                for (int n = 0; n < 16; n++) {
                    float s = acc[r][n];
                    g_dt[(row0 + r) * HH + n] = fmaxf(s, 0.f) + log1pf(expf(-fabsf(s)));
                }
        }
    }
}

// ---------------------------------------------------------------------------
// GEMM common constants
// ---------------------------------------------------------------------------
#define GK 1024
#define GN 1024
#define NCHUNK 16
#define BUF_STRIDE 98304
#define GIDESC ((1u<<4)|(1u<<7)|(1u<<10)|((256u/8)<<17)|((128u/16)<<24))

// ---------------------------------------------------------------------------
// gemm3: merged projection GEMM. grid=(12,128). mode=bn>>2: 0=c 1=b 2=x.
// ---------------------------------------------------------------------------
__global__ __launch_bounds__(256, 1) void gemm3(
        const char* __restrict__ Ahi, const char* __restrict__ Alo,
        const char* __restrict__ Whi, const char* __restrict__ Wlo,
        const float* __restrict__ cosp, const float* __restrict__ sinp,
        char* __restrict__ tch, char* __restrict__ tcl,
        char* __restrict__ tbh, char* __restrict__ tbl,
        float* __restrict__ px) {
    extern __shared__ char sm[];
    int tid = threadIdx.x;
    int wid = tid >> 5, lid = tid & 31;
    int bn = blockIdx.x, bm = blockIdx.y;
    int mode = bn >> 2;
#if HAS_TCGEN05
    uint32_t sbase = smem_u32(sm);
    if (tid == 0) {
        MBAR_INIT(sbase + 8, 1);  MBAR_INIT(sbase + 16, 1);
        MBAR_INIT(sbase + 24, 1); MBAR_INIT(sbase + 32, 1);
    }
    if (wid == 0) TC_ALLOC(sbase, 256);
    __syncthreads();
    uint32_t tmem;
    asm volatile("ld.shared.b32 %0, [%1];" : "=r"(tmem) : "r"(sbase));

    if (wid == 0 && elect_one()) {
        auto load = [&](int chunk, int b) {
            uint32_t mb = sbase + 8 + (uint32_t)b * 8;
            MBAR_EXPECT_TX(mb, 98304u);
            uint32_t d = sbase + 1024u + (uint32_t)b * BUF_STRIDE;
            size_t ao = ((size_t)bm * 16 + chunk) << 14;
            size_t bo = ((size_t)bn * 16 + chunk) << 15;
            BULK_G2S(d,          Ahi + ao, 16384u, mb);
            BULK_G2S(d + 16384,  Alo + ao, 16384u, mb);
            BULK_G2S(d + 32768,  Whi + bo, 32768u, mb);
            BULK_G2S(d + 65536,  Wlo + bo, 32768u, mb);
        };
        load(0, 0);
        load(1, 1);
        int f0 = 0, f1 = 0, e0 = 0, e1 = 0;
        for (int k = 0; k < NCHUNK; k++) {
            int b = k & 1;
            if (b == 0) { MBAR_WAIT(sbase + 8, f0);  f0 ^= 1; }
            else        { MBAR_WAIT(sbase + 16, f1); f1 ^= 1; }
            uint32_t boff = sbase + 1024u + (uint32_t)b * BUF_STRIDE;
            uint64_t dah = mk_desc(boff);
            uint64_t dal = mk_desc(boff + 16384);
            uint64_t dbh = mk_desc(boff + 32768);
            uint64_t dbl = mk_desc(boff + 65536);
#pragma unroll
            for (int ks = 0; ks < 4; ks++) {
                mma_f16_ss(tmem, dah + ks*2, dbh + ks*2, GIDESC,
                           (k == 0 && ks == 0) ? 0u : 1u);
                mma_f16_ss(tmem, dah + ks*2, dbl + ks*2, GIDESC, 1u);
                mma_f16_ss(tmem, dal + ks*2, dbh + ks*2, GIDESC, 1u);
            }
            TC_COMMIT(sbase + 24 + (uint32_t)b * 8);
            if (k + 2 < NCHUNK) {
                if (b == 0) { MBAR_WAIT(sbase + 24, e0); e0 ^= 1; }
                else        { MBAR_WAIT(sbase + 32, e1); e1 ^= 1; }
                load(k + 2, b);
            }
        }
        MBAR_WAIT(sbase + 24, e0);
        MBAR_WAIT(sbase + 32, e1);
    }
    __syncthreads();
    TC_FENCE_AFTER();

    {
        int sub = wid & 3, grp = wid >> 2;
        int row = bm * 128 + sub * 32 + lid;
        if (mode < 2) {
            char* Thi = (mode == 0) ? tch : tbh;
            char* Tlo = (mode == 0) ? tcl : tbl;
            const float* cr = cosp + (size_t)row * 64;
            const float* sr = sinp + (size_t)row * 64;
            uint32_t rb = (uint32_t)(row & 127) * 128;
#pragma unroll
            for (int cb2 = 0; cb2 < 2; cb2++) {
                int head64 = (grp * 2 + cb2) * 64;
                uint32_t r0[32], r1[32];
                ldtm32(r0, tmem + head64);      TC_WAIT_LD();
                ldtm32(r1, tmem + head64 + 32); TC_WAIT_LD();
                int hidx = (bn & 3) * 4 + grp * 2 + cb2;
                size_t tb = ((size_t)((row >> 7) * HH + hidx)) << 14;
#pragma unroll
                for (int j = 0; j < 32; j += 4) {
                    float4 c1 = *(const float4*)(cr + j);
                    float4 s1 = *(const float4*)(sr + j);
                    float4 c2 = *(const float4*)(cr + j + 32);
                    float4 s2 = *(const float4*)(sr + j + 32);
                    float a0 = __uint_as_float(r0[j]),   a1 = __uint_as_float(r0[j+1]);
                    float a2 = __uint_as_float(r0[j+2]), a3 = __uint_as_float(r0[j+3]);
                    float q0 = __uint_as_float(r1[j]),   q1 = __uint_as_float(r1[j+1]);
                    float q2 = __uint_as_float(r1[j+2]), q3 = __uint_as_float(r1[j+3]);
                    uint2 h1, l1, h2, l2;
                    split_pack2(a0*c1.x - q0*s1.x, a1*c1.y - q1*s1.y, h1.x, l1.x);
                    split_pack2(a2*c1.z - q2*s1.z, a3*c1.w - q3*s1.w, h1.y, l1.y);
                    split_pack2(q0*c2.x + a0*s2.x, q1*c2.y + a1*s2.y, h2.x, l2.x);
                    split_pack2(q2*c2.z + a2*s2.z, q3*c2.w + a3*s2.w, h2.y, l2.y);
                    uint32_t o1 = swz(rb + j * 2);
                    uint32_t o2 = swz(rb + 64 + j * 2);
                    *(uint2*)(Thi + tb + o1) = h1;
                    *(uint2*)(Tlo + tb + o1) = l1;
                    *(uint2*)(Thi + tb + o2) = h2;
                    *(uint2*)(Tlo + tb + o2) = l2;
                }
            }
        } else {
            int bnc = (bn & 3) * 256;
            float* crow = px + (size_t)row * GN + bnc;
#pragma unroll
            for (int cb2 = 0; cb2 < 2; cb2++) {
                int head64 = (grp * 2 + cb2) * 64;
                uint32_t r0[32], r1[32];
                ldtm32(r0, tmem + head64);      TC_WAIT_LD();
                ldtm32(r1, tmem + head64 + 32); TC_WAIT_LD();
                int hidx = (bnc >> 6) + grp * 2 + cb2;
                float dtv = g_dt[row * HH + hidx];
#pragma unroll
                for (int j = 0; j < 32; j += 4) {
                    float4 o1 = make_float4(__uint_as_float(r0[j])   * dtv,
                                            __uint_as_float(r0[j+1]) * dtv,
                                            __uint_as_float(r0[j+2]) * dtv,
                                            __uint_as_float(r0[j+3]) * dtv);
                    float4 o2 = make_float4(__uint_as_float(r1[j])   * dtv,
                                            __uint_as_float(r1[j+1]) * dtv,
                                            __uint_as_float(r1[j+2]) * dtv,
                                            __uint_as_float(r1[j+3]) * dtv);
                    *(float4*)(crow + head64 + j)      = o1;
                    *(float4*)(crow + head64 + 32 + j) = o2;
                }
            }
        }
        TC_FENCE_BEFORE();
    }
    __syncthreads();
    if (wid == 0) TC_DEALLOC(tmem, 256);
#else
    // CUDA-core fallback
    int tx = tid & 15, ty = tid >> 4;
    int bmr = bm * 128;
    float* sA = (float*)sm;
    float* sB = (float*)(sm + 8192);
    float* stg = (float*)(sm + 16384);
    auto rdA = [&](const char* p, int row, int k) {
        return __bfloat162float(*(const __nv_bfloat16*)(p + a_tile_off(row, k)));
    };
    auto rdBW = [&](const char* p, int gn, int k) {
        uint32_t tile = (uint32_t)(gn >> 8) * 16u + (uint32_t)(k >> 6);
        uint32_t off = (tile << 15) + swz(((uint32_t)(gn & 255) << 7) + ((uint32_t)(k & 63) << 1));
        return __bfloat162float(*(const __nv_bfloat16*)(p + off));
    };
    for (int half = 0; half < 2; half++) {
        int bn2 = bn * 256 + half * 128;
        float acc[8][8];
#pragma unroll
        for (int i = 0; i < 8; i++)
#pragma unroll
            for (int j = 0; j < 8; j++) acc[i][j] = 0.f;
        for (int k0 = 0; k0 < GK; k0 += 16) {
            for (int i = tid; i < 2048; i += 256) {
                int r = i >> 4, kk = i & 15;
                sA[kk*128 + r] = rdA(Ahi, bmr + r, k0 + kk) + rdA(Alo, bmr + r, k0 + kk);
                sB[kk*128 + r] = rdBW(Whi, bn2 + r, k0 + kk) + rdBW(Wlo, bn2 + r, k0 + kk);
            }
            __syncthreads();
#pragma unroll
            for (int kk = 0; kk < 16; kk++) {
                float a[8], b[8];
#pragma unroll
                for (int i = 0; i < 4; i++) {
                    a[i] = sA[kk*128 + ty*4 + i];
                    a[i+4] = sA[kk*128 + 64 + ty*4 + i];
                    b[i] = sB[kk*128 + tx*4 + i];
                    b[i+4] = sB[kk*128 + 64 + tx*4 + i];
                }
#pragma unroll
                for (int i = 0; i < 8; i++)
#pragma unroll
                    for (int j = 0; j < 8; j++) acc[i][j] += a[i] * b[j];
            }
            __syncthreads();
        }
#pragma unroll
        for (int i = 0; i < 8; i++) {
            int rl = (i < 4) ? (ty*4 + i) : (64 + ty*4 + i - 4);
#pragma unroll
            for (int j = 0; j < 8; j++) {
                int cl = (j < 4) ? (tx*4 + j) : (64 + tx*4 + j - 4);
                stg[rl * 128 + cl] = acc[i][j];
            }
        }
        __syncthreads();
        if (mode < 2) {
            char* Thi = (mode == 0) ? tch : tbh;
            char* Tlo = (mode == 0) ? tcl : tbl;
            for (int u = tid; u < 128 * 64; u += 256) {
                int rr = u >> 6, ps = u & 63;
                int head = ps >> 5, p = ps & 31;
                int row = bmr + rr;
                float a = stg[rr*128 + head*64 + p];
                float q = stg[rr*128 + head*64 + p + 32];
                float c1 = cosp[row*64 + p],      s1 = sinp[row*64 + p];
                float c2 = cosp[row*64 + p + 32], s2 = sinp[row*64 + p + 32];
                float v1 = a * c1 - q * s1;
                float v2 = q * c2 + a * s2;
                int hidx = (bn & 3) * 4 + half * 2 + head;
                float hh, llv;
                split2(v1, hh, llv);
                size_t o = cb_off(row, hidx, p);
                *(__nv_bfloat16*)(Thi + o) = __float2bfloat16(hh);
                *(__nv_bfloat16*)(Tlo + o) = __float2bfloat16(llv);
                split2(v2, hh, llv);
                o = cb_off(row, hidx, p + 32);
                *(__nv_bfloat16*)(Thi + o) = __float2bfloat16(hh);
                *(__nv_bfloat16*)(Tlo + o) = __float2bfloat16(llv);
            }
        } else {
            int bnc = (bn & 3) * 256 + half * 128;
            for (int u = tid; u < 128 * 128; u += 256) {
                int rr = u >> 7, cl = u & 127;
                int row = bmr + rr;
                int hidx = (bnc + cl) >> 6;
                px[(size_t)row * GN + bnc + cl] = stg[rr*128 + cl] * g_dt[row * HH + hidx];
            }
        }
        __syncthreads();
    }
#endif
}

// ---------------------------------------------------------------------------
// gemm_t: plain GEMM (final Wout). grid=(4,128).
// ---------------------------------------------------------------------------
__global__ __launch_bounds__(256, 1) void gemm_t(
        const char* __restrict__ Ahi, const char* __restrict__ Alo,
        const char* __restrict__ Bhi, const char* __restrict__ Blo,
        float* __restrict__ C) {
    extern __shared__ char sm[];
#if HAS_TCGEN05
    uint32_t sbase = smem_u32(sm);
    int tid = threadIdx.x;
    int wid = tid >> 5, lid = tid & 31;
    int bn = blockIdx.x, bm = blockIdx.y;

    if (tid == 0) {
        MBAR_INIT(sbase + 8, 1);  MBAR_INIT(sbase + 16, 1);
        MBAR_INIT(sbase + 24, 1); MBAR_INIT(sbase + 32, 1);
    }
    if (wid == 0) TC_ALLOC(sbase, 256);
    __syncthreads();
    uint32_t tmem;
    asm volatile("ld.shared.b32 %0, [%1];" : "=r"(tmem) : "r"(sbase));

    if (wid == 0 && elect_one()) {
        auto load = [&](int chunk, int b) {
            uint32_t mb = sbase + 8 + (uint32_t)b * 8;
            MBAR_EXPECT_TX(mb, 98304u);
            uint32_t d = sbase + 1024u + (uint32_t)b * BUF_STRIDE;
            size_t ao = ((size_t)bm * 16 + chunk) << 14;
            size_t bo = ((size_t)bn * 16 + chunk) << 15;
            BULK_G2S(d,          Ahi + ao, 16384u, mb);
            BULK_G2S(d + 16384,  Alo + ao, 16384u, mb);
            BULK_G2S(d + 32768,  Bhi + bo, 32768u, mb);
            BULK_G2S(d + 65536,  Blo + bo, 32768u, mb);
        };
        load(0, 0);
        load(1, 1);
        int f0 = 0, f1 = 0, e0 = 0, e1 = 0;
        for (int k = 0; k < NCHUNK; k++) {
            int b = k & 1;
            if (b == 0) { MBAR_WAIT(sbase + 8, f0);  f0 ^= 1; }
            else        { MBAR_WAIT(sbase + 16, f1); f1 ^= 1; }
            uint32_t boff = sbase + 1024u + (uint32_t)b * BUF_STRIDE;
            uint64_t dah = mk_desc(boff);
            uint64_t dal = mk_desc(boff + 16384);
            uint64_t dbh = mk_desc(boff + 32768);
            uint64_t dbl = mk_desc(boff + 65536);
#pragma unroll
            for (int ks = 0; ks < 4; ks++) {
                mma_f16_ss(tmem, dah + ks*2, dbh + ks*2, GIDESC,
                           (k == 0 && ks == 0) ? 0u : 1u);
                mma_f16_ss(tmem, dah + ks*2, dbl + ks*2, GIDESC, 1u);
                mma_f16_ss(tmem, dal + ks*2, dbh + ks*2, GIDESC, 1u);
            }
            TC_COMMIT(sbase + 24 + (uint32_t)b * 8);
            if (k + 2 < NCHUNK) {
                if (b == 0) { MBAR_WAIT(sbase + 24, e0); e0 ^= 1; }
                else        { MBAR_WAIT(sbase + 32, e1); e1 ^= 1; }
                load(k + 2, b);
            }
        }
        MBAR_WAIT(sbase + 24, e0);
        MBAR_WAIT(sbase + 32, e1);
    }
    __syncthreads();
    TC_FENCE_AFTER();

    {
        int sub = wid & 3, grp = wid >> 2;
        int row = bm * 128 + sub * 32 + lid;
        float* crow = C + (size_t)row * GN + bn * 256;
#pragma unroll
        for (int cb = grp * 4; cb < grp * 4 + 4; cb++) {
            uint32_t r[32];
            ldtm32(r, tmem + cb * 32);
            TC_WAIT_LD();
#pragma unroll
            for (int j = 0; j < 8; j++) {
                float4 v = make_float4(__uint_as_float(r[j*4]), __uint_as_float(r[j*4+1]),
                                       __uint_as_float(r[j*4+2]), __uint_as_float(r[j*4+3]));
                *(float4*)(crow + cb * 32 + j * 4) = v;
            }
        }
        TC_FENCE_BEFORE();
    }
    __syncthreads();
    if (wid == 0) TC_DEALLOC(tmem, 256);
#else
    int tid = threadIdx.x;
    int tx = tid & 15, ty = tid >> 4;
    int bn = blockIdx.x * 256, bm = blockIdx.y * 128;
    float* sA = (float*)sm;
    float* sB = (float*)(sm + 8192);
    auto rdA = [&](const char* p, int row, int k) {
        return __bfloat162float(*(const __nv_bfloat16*)(p + a_tile_off(row, k)));
    };
    auto rdB = [&](const char* p, int n, int k) {
        return __bfloat162float(*(const __nv_bfloat16*)(p + b_tile_off(n, k)));
    };
    for (int half = 0; half < 2; half++) {
        int bn2 = bn + half * 128;
        float acc[8][8];
#pragma unroll
        for (int i = 0; i < 8; i++)
#pragma unroll
            for (int j = 0; j < 8; j++) acc[i][j] = 0.f;
        for (int k0 = 0; k0 < GK; k0 += 16) {
            for (int i = tid; i < 2048; i += 256) {
                int r = i >> 4, kk = i & 15;
                sA[kk*128 + r] = rdA(Ahi, bm + r, k0 + kk) + rdA(Alo, bm + r, k0 + kk);
                sB[kk*128 + r] = rdB(Bhi, bn2 + r, k0 + kk) + rdB(Blo, bn2 + r, k0 + kk);
            }
            __syncthreads();
#pragma unroll
            for (int kk = 0; kk < 16; kk++) {
                float a[8], b[8];
#pragma unroll
                for (int i = 0; i < 4; i++) {
                    a[i] = sA[kk*128 + ty*4 + i];
                    a[i+4] = sA[kk*128 + 64 + ty*4 + i];
                    b[i] = sB[kk*128 + tx*4 + i];
                    b[i+4] = sB[kk*128 + 64 + tx*4 + i];
                }
#pragma unroll
                for (int i = 0; i < 8; i++)
#pragma unroll
                    for (int j = 0; j < 8; j++) acc[i][j] += a[i] * b[j];
            }
            __syncthreads();
        }
#pragma unroll
        for (int i = 0; i < 8; i++) {
            int row = bm + ((i < 4) ? (ty*4 + i) : (64 + ty*4 + i - 4));
#pragma unroll
            for (int j = 0; j < 8; j++) {
                int col = bn2 + ((j < 4) ? (tx*4 + j) : (64 + tx*4 + j - 4));
                C[(size_t)row * GN + col] = acc[i][j];
            }
        }
        __syncthreads();
    }
#endif
}

// ---------------------------------------------------------------------------
// kb: fused acum (per-chunk cumsum of dt*A) + chunk states.
// ---------------------------------------------------------------------------
__global__ __launch_bounds__(256) void kb_kernel(const char* __restrict__ tbh,
                                                 const char* __restrict__ tbl,
                                                 const float* __restrict__ A) {
    __shared__ float sX[4096];
    __shared__ float sB[4096];
    __shared__ float sac[256];
    int bid = blockIdx.x;
    int h = bid & 15, c = (bid >> 4) & 31, b = bid >> 9;
    int tid = threadIdx.x, tx = tid & 15, ty = tid >> 4;
    int chunk_row = b * LL + c * CLc;

    sac[tid] = g_dt[(chunk_row + tid) * HH + h] * A[h];
    __syncthreads();
    for (int off = 1; off < 256; off <<= 1) {
        float u = (tid >= off) ? sac[tid - off] : 0.f;
        __syncthreads();
        sac[tid] += u;
        __syncthreads();
    }
    g_ac[(chunk_row + tid) * HH + h] = sac[tid];
    if (tid == 255) g_cdec[bid] = expf(sac[255]);
    __syncthreads();
    float aclast = sac[255];

    float acc[4][4];
#pragma unroll
    for (int i = 0; i < 4; i++)
#pragma unroll
        for (int j = 0; j < 4; j++) acc[i][j] = 0.f;

    for (int ltile = 0; ltile < 4; ltile++) {
        int r0 = chunk_row + ltile * 64;
#pragma unroll
        for (int t = 0; t < 2; t++) {
            int u = tid + t * 256;
            int rr = u >> 3, p8 = (u & 7) * 8;
            int row = r0 + rr;
            size_t to = (((size_t)((row >> 7) * HH + h)) << 14) +
                        swz(((uint32_t)(row & 127) << 7) + ((uint32_t)p8 << 1));
            uint4 hv = *(const uint4*)(tbh + to);
            uint4 lv = *(const uint4*)(tbl + to);
            float w = __expf(aclast - sac[ltile * 64 + rr]);
            float2 f0 = unsplit2(hv.x, lv.x);
            float2 f1 = unsplit2(hv.y, lv.y);
            float2 f2 = unsplit2(hv.z, lv.z);
            float2 f3 = unsplit2(hv.w, lv.w);
            *(float4*)&sB[rr*64 + p8]     = make_float4(f0.x*w, f0.y*w, f1.x*w, f1.y*w);
            *(float4*)&sB[rr*64 + p8 + 4] = make_float4(f2.x*w, f2.y*w, f3.x*w, f3.y*w);
            const float* xx = g_x + (size_t)row * DD + h * 64 + p8;
            *(float4*)&sX[rr*64 + p8]     = *(const float4*)xx;
            *(float4*)&sX[rr*64 + p8 + 4] = *(const float4*)(xx + 4);
        }
        __syncthreads();
#pragma unroll 4
        for (int l = 0; l < 64; l++) {
            float xv[4], bv[4];
#pragma unroll
            for (int i = 0; i < 4; i++) xv[i] = sX[l * 64 + ty * 4 + i];
#pragma unroll
            for (int j = 0; j < 4; j++) bv[j] = sB[l * 64 + tx * 4 + j];
#pragma unroll
            for (int i = 0; i < 4; i++)
#pragma unroll
                for (int j = 0; j < 4; j++) acc[i][j] += xv[i] * bv[j];
        }
        __syncthreads();
    }
    int sb = ((b * NCC + c) * HH + h) * 4096;
#pragma unroll
    for (int i = 0; i < 4; i++) {
        float4 v = make_float4(acc[i][0], acc[i][1], acc[i][2], acc[i][3]);
        *(float4*)&g_states[sb + (ty * 4 + i) * 64 + tx * 4] = v;
    }
}

// ---------------------------------------------------------------------------
// kc: sequential chunk scan, one element per thread. grid = BB*HH*16.
// ---------------------------------------------------------------------------
__global__ __launch_bounds__(256) void kc_kernel(float* __restrict__ fs) {
    int bid = blockIdx.x;
    int ks = bid & 15;
    int h = (bid >> 4) & 15;
    int b = bid >> 8;
    int e = ks * 256 + threadIdx.x;
    int bh = b * NCC * HH + h;
    float st = 0.f;
#pragma unroll 4
    for (int c = 0; c < NCC; c++) {
        float dec = g_cdec[(b * NCC + c) * HH + h];
        int base = (bh + c * HH) * 4096 + e;
        g_prev[base] = st;
        st = st * dec + g_states[base];
    }
    fs[(b * HH + h) * 4096 + e] = st;
}

// ---------------------------------------------------------------------------
// Flash kernel: early MMA1 issue; separate S slice buffers (no MMA2 wait).
// S sl0 -> FO_BHI/FO_BLO; S sl1 -> FO_S1H / FO_CHI (C free after off-term).
// ---------------------------------------------------------------------------
#define FL_SMEM 216064
#define FO_AC   64
#define FO_EC   1088
#define FO_CHI  3072
#define FO_CLO  19456
#define FO_BHI  35840
#define FO_BLO  68608
#define FO_XHI  101376
#define FO_XLO  134144
#define FO_PHI  166912
#define FO_PLO  175104
#define FO_S1H  183296

__global__ __launch_bounds__(256, 1) void flash_k(const char* __restrict__ tch,
                                                  const char* __restrict__ tcl,
                                                  const char* __restrict__ tbh,
                                                  const char* __restrict__ tbl,
                                                  char* __restrict__ yhi,
                                                  char* __restrict__ ylo) {
    extern __shared__ char sm[];
    int tid = threadIdx.x, wid = tid >> 5, lid = tid & 31;
    int bid = blockIdx.x;
    int half = bid & 1, h = (bid >> 1) & 15, c = (bid >> 5) & 31, b = bid >> 10;
    int chunk_row = b * LL + c * CLc;
    int l0g = half * 128;
    int SL = half ? 256 : 128;
    float* acs = (float*)(sm + FO_AC);
    float* ecol = (float*)(sm + FO_EC);

#if HAS_TCGEN05
    uint32_t sbase = smem_u32(sm);
    int nsl = SL / 128;
    if (tid == 0) {
        MBAR_INIT(sbase + 8, 1);  MBAR_INIT(sbase + 16, 1);
        MBAR_INIT(sbase + 24, 1); MBAR_INIT(sbase + 32, 1);
        MBAR_INIT(sbase + 40, 1);
    }
    if (wid == 0) TC_ALLOC(sbase, 512);
    __syncthreads();
    uint32_t tmem;
    asm volatile("ld.shared.b32 %0, [%1];" : "=r"(tmem) : "r"(sbase));

    if (tid == 0) {
        uint32_t nbytes = 32768u * (uint32_t)(1 + nsl);
        MBAR_EXPECT_TX(sbase + 40, nbytes);
        size_t ct = ((size_t)(((chunk_row + l0g) >> 7) * HH + h)) << 14;
        BULK_G2S(sbase + FO_CHI, tch + ct, 16384u, sbase + 40);
        BULK_G2S(sbase + FO_CLO, tcl + ct, 16384u, sbase + 40);
        for (int i = 0; i < nsl; i++) {
            size_t bt = ((size_t)(((chunk_row >> 7) + i) * HH + h)) << 14;
            BULK_G2S(sbase + FO_BHI + (uint32_t)i * 16384u, tbh + bt, 16384u, sbase + 40);
            BULK_G2S(sbase + FO_BLO + (uint32_t)i * 16384u, tbl + bt, 16384u, sbase + 40);
        }
    }

    acs[tid] = g_ac[(chunk_row + tid) * HH + h];
    __syncthreads();
    ecol[tid] = __expf(acs[tid & ~31] - acs[tid]);

    // EARLY MMA1 issue (needs only bulk C/B tiles) — overlaps the X/P fills.
    if (wid == 0 && elect_one()) {
        MBAR_WAIT(sbase + 40, 0);
        uint64_t dCh = mk_desc(sbase + FO_CHI), dCl = mk_desc(sbase + FO_CLO);
        uint64_t dBh = mk_desc(sbase + FO_BHI), dBl = mk_desc(sbase + FO_BLO);
        uint32_t id1 = (SL == 128) ? IDESC_N(128) : IDESC_N(256);
#pragma unroll
        for (int ks = 0; ks < 4; ks++) {
            mma_f16_ss(tmem, dCh + ks*2, dBh + ks*2, id1, ks > 0);
            mma_f16_ss(tmem, dCh + ks*2, dBl + ks*2, id1, 1);
            mma_f16_ss(tmem, dCl + ks*2, dBh + ks*2, id1, 1);
        }
        TC_COMMIT(sbase + 8);
    }

    // X^T tile fill
    for (int t = 0; t < SL/16; t++) {
        int u = tid + t * 256;
        int p = u & 63, sg = u >> 6;
        int s0 = sg * 4;
        float xv[4];
#pragma unroll
        for (int i = 0; i < 4; i++)
            xv[i] = g_x[(size_t)(chunk_row + s0 + i) * DD + h*64 + p];
        uint2 hv, lv;
        split_pack2(xv[0], xv[1], hv.x, lv.x);
        split_pack2(xv[2], xv[3], hv.y, lv.y);
        uint32_t off = swz((uint32_t)(((p>>3) + (s0>>6)*8)*1024 + (p&7)*128 + (s0&63)*2));
        *(uint2*)(sm + FO_XHI + off) = hv;
        *(uint2*)(sm + FO_XLO + off) = lv;
    }
    // prev tile fill
    {
        int pbase = ((b * NCC + c) * HH + h) * 4096;
#pragma unroll
        for (int t = 0; t < 4; t++) {
            int u = tid + t * 256;
            int p = u >> 4, n4 = (u & 15) * 4;
            float4 v = *(const float4*)(g_prev + pbase + p*64 + n4);
            uint2 hv, lv;
            split_pack2(v.x, v.y, hv.x, lv.x);
            split_pack2(v.z, v.w, hv.y, lv.y);
            uint32_t off = swz((uint32_t)(p*128 + n4*2));
            *(uint2*)(sm + FO_PHI + off) = hv;
            *(uint2*)(sm + FO_PLO + off) = lv;
        }
    }
    FENCE_ASYNC();
    __syncthreads();

    // off-term MMA (needs P tile)
    if (wid == 0 && elect_one()) {
        uint64_t dCh = mk_desc(sbase + FO_CHI), dCl = mk_desc(sbase + FO_CLO);
        uint64_t dPh = mk_desc(sbase + FO_PHI), dPl = mk_desc(sbase + FO_PLO);
        uint32_t id64 = IDESC_N(64);
#pragma unroll
        for (int ks = 0; ks < 4; ks++) {
            mma_f16_ss(tmem + 320, dCh + ks*2, dPh + ks*2, id64, ks > 0);
            mma_f16_ss(tmem + 320, dCh + ks*2, dPl + ks*2, id64, 1);
            mma_f16_ss(tmem + 320, dCl + ks*2, dPh + ks*2, id64, 1);
        }
        TC_COMMIT(sbase + 16);
    }
    MBAR_WAIT(sbase + 8, 0);
    TC_FENCE_AFTER();

    int sub = wid & 3, grp = wid >> 2;
    int lrow = sub * 32 + lid;
    float acl = acs[l0g + lrow];

    float erow[8];
#pragma unroll
    for (int j = 0; j < 8; j++) erow[j] = __expf(acl - acs[j * 32]);

    for (int sl = 0; sl < nsl; sl++) {
        uint32_t sbh = (sl == 0) ? FO_BHI : FO_S1H;
        uint32_t sbl = (sl == 0) ? FO_BLO : FO_CHI;
        if (sl == 1) MBAR_WAIT(sbase + 16, 0);   // off-term done -> C smem free
#pragma unroll
        for (int rd = grp; rd < 4; rd += 2) {
            uint32_t r[32];
            ldtm32(r, tmem + sl*128 + rd*32);
            TC_WAIT_LD();
            int colbase = sl*128 + rd*32;
            float er = erow[colbase >> 5];
#pragma unroll
            for (int j = 0; j < 32; j += 4) {
                float vv[4];
#pragma unroll
                for (int i = 0; i < 4; i++) {
                    int cg = colbase + j + i;
                    float v = __uint_as_float(r[j+i]) * er * ecol[cg];
                    vv[i] = (cg <= l0g + lrow) ? v : 0.f;
                }
                uint2 hv, lv;
                split_pack2(vv[0], vv[1], hv.x, lv.x);
                split_pack2(vv[2], vv[3], hv.y, lv.y);
                int sIn = rd*32 + j;
                uint32_t off = swz((uint32_t)(((lrow>>3) + (sIn>>6)*16)*1024
                                              + (lrow&7)*128 + (sIn&63)*2));
                *(uint2*)(sm + sbh + off) = hv;
                *(uint2*)(sm + sbl + off) = lv;
            }
        }
        FENCE_ASYNC();
        __syncthreads();
        if (wid == 0 && elect_one()) {
            uint64_t dSh = mk_desc(sbase + sbh), dSl = mk_desc(sbase + sbl);
            uint64_t dXh = mk_desc(sbase + FO_XHI), dXl = mk_desc(sbase + FO_XLO);
            uint32_t id64 = IDESC_N(64);
#pragma unroll
            for (int ks2 = 0; ks2 < 8; ks2++) {
                int ksg = sl*8 + ks2;
                uint64_t ao = (uint64_t)((ks2 >> 2)*1024 + (ks2 & 3)*2);
                uint64_t bo = (uint64_t)((ksg >> 2)*512 + (ksg & 3)*2);
                mma_f16_ss(tmem + 256, dSh + ao, dXh + bo, id64,
                           !(sl == 0 && ks2 == 0));
                mma_f16_ss(tmem + 256, dSh + ao, dXl + bo, id64, 1);
                mma_f16_ss(tmem + 256, dSl + ao, dXh + bo, id64, 1);
            }
            TC_COMMIT(sbase + 24 + (uint32_t)sl * 8);
        }
    }
    MBAR_WAIT(sbase + 24, 0);
    if (nsl == 2) { MBAR_WAIT(sbase + 32, 0); }
    else          { MBAR_WAIT(sbase + 16, 0); }
    TC_FENCE_AFTER();

    {
        int row = chunk_row + l0g + lrow;
        uint32_t tile = (uint32_t)(row >> 7) * 16u + (uint32_t)h;
        char* dhi = yhi + ((size_t)tile << 14);
        char* dlo = ylo + ((size_t)tile << 14);
        float e = __expf(acl);
        uint32_t y1[32], y2[32];
        ldtm32(y1, tmem + 256 + grp*32);
        ldtm32(y2, tmem + 320 + grp*32);
        TC_WAIT_LD();
#pragma unroll
        for (int j = 0; j < 32; j += 4) {
            float vv[4];
#pragma unroll
            for (int i = 0; i < 4; i++)
                vv[i] = __uint_as_float(y1[j+i]) + e * __uint_as_float(y2[j+i]);
            uint2 hv, lv;
            split_pack2(vv[0], vv[1], hv.x, lv.x);
            split_pack2(vv[2], vv[3], hv.y, lv.y);
            uint32_t off = swz((uint32_t)((row & 127)*128 + (grp*32 + j)*2));
            *(uint2*)(dhi + off) = hv;
            *(uint2*)(dlo + off) = lv;
        }
        TC_FENCE_BEFORE();
    }
    __syncthreads();
    if (wid == 0) TC_DEALLOC(tmem, 512);
#else
    // CUDA-core fallback
    float* sC = (float*)(sm + FO_CHI);
    float* sS = (float*)(sm + FO_BHI);
    float* sB = (float*)(sm + FO_BLO);
    float* sX = (float*)(sm + FO_XHI);
    float* sP = (float*)(sm + FO_XLO);
    int tx = tid & 15, ty = tid >> 4;

    acs[tid] = g_ac[(chunk_row + tid) * HH + h];
    for (int t = 0; t < 16; t++) {
        int pr = tid + t * 256;
        int rr = pr >> 5, pp = pr & 31;
        int row = chunk_row + l0g + rr;
        sC[rr*64 + pp]      = ld_cb(tch, tcl, row, h, pp);
        sC[rr*64 + pp + 32] = ld_cb(tch, tcl, row, h, pp + 32);
    }
    {
        int pbase = ((b * NCC + c) * HH + h) * 4096;
        for (int t = 0; t < 16; t++) {
            int idx = tid + t * 256;
            sP[idx] = g_prev[pbase + idx];
        }
    }
    __syncthreads();

    float accD[8][4], accO[8][4];
#pragma unroll
    for (int i = 0; i < 8; i++)
#pragma unroll
        for (int j = 0; j < 4; j++) { accD[i][j] = 0.f; accO[i][j] = 0.f; }
    for (int n = 0; n < 64; n++)
#pragma unroll
        for (int i = 0; i < 8; i++)
#pragma unroll
            for (int j = 0; j < 4; j++)
                accO[i][j] += sC[(ty*8+i)*64 + n] * sP[(tx*4+j)*64 + n];

    for (int stile = 0; stile < SL/64; stile++) {
        for (int t = 0; t < 8; t++) {
            int pr = tid + t * 256;
            int rr = pr >> 5, pp = pr & 31;
            int row = chunk_row + stile*64 + rr;
            sB[rr*64 + pp]      = ld_cb(tbh, tbl, row, h, pp);
            sB[rr*64 + pp + 32] = ld_cb(tbh, tbl, row, h, pp + 32);
            const float* xx = g_x + (size_t)row * DD + h * 64;
            sX[rr*64 + pp]      = xx[pp];
            sX[rr*64 + pp + 32] = xx[pp + 32];
        }
        __syncthreads();
        for (int t = 0; t < 32; t++) {
            int idx = tid + t * 256;
            int l = idx >> 6, sIn = idx & 63;
            int sg = stile*64 + sIn;
            float v = 0.f;
            if (sg <= l0g + l) {
                for (int n = 0; n < 64; n++)
                    v += sC[l*64 + n] * sB[sIn*64 + n];
                v *= expf(acs[l0g + l] - acs[sg]);
            }
            sS[idx] = v;
        }
        __syncthreads();
        for (int s = 0; s < 64; s++)
#pragma unroll
            for (int i = 0; i < 8; i++)
#pragma unroll
                for (int j = 0; j < 4; j++)
                    accD[i][j] += sS[(ty*8+i)*64 + s] * sX[s*64 + tx*4 + j];
        __syncthreads();
    }
#pragma unroll
    for (int i = 0; i < 8; i++) {
        int lr = ty*8 + i;
        int row = chunk_row + l0g + lr;
        float e = expf(acs[l0g + lr]);
        uint32_t tile = (uint32_t)(row >> 7) * 16u + (uint32_t)h;
#pragma unroll
        for (int j = 0; j < 4; j++) {
            float v = accD[i][j] + e * accO[i][j];
            float hh, llv;
            split2(v, hh, llv);
            int col = tx*4 + j;
            uint32_t off = ((uint32_t)tile << 14) +
                           swz((uint32_t)((row & 127)*128 + col*2));
            *(__nv_bfloat16*)(yhi + off) = __float2bfloat16(hh);
            *(__nv_bfloat16*)(ylo + off) = __float2bfloat16(llv);
        }
    }
#endif
}

// ---------------------------------------------------------------------------
// kernel_launch
// ---------------------------------------------------------------------------
extern "C" void kernel_launch(void* const* d_in, const int* in_sizes, int n_in,
                              void* d_out, int out_size) {
    (void)in_sizes; (void)n_in; (void)out_size;
    const float* hs   = (const float*)d_in[0];
    const float* cosp = (const float*)d_in[1];
    const float* sinp = (const float*)d_in[2];
    const float* Wc   = (const float*)d_in[3];
    const float* Wb   = (const float*)d_in[4];
    const float* Wdt  = (const float*)d_in[5];
    const float* Wx   = (const float*)d_in[6];
    const float* Wout = (const float*)d_in[7];
    const float* A    = (const float*)d_in[8];
    float* out = (float*)d_out;
    float* fs  = out + (size_t)MM * DD;

    float *px;
    char *ahi, *alo, *whi, *wlo, *tch, *tcl, *tbh, *tbl;
    cudaGetSymbolAddress((void**)&px, g_x);
    cudaGetSymbolAddress((void**)&ahi, g_ahi);
    cudaGetSymbolAddress((void**)&alo, g_alo);
    cudaGetSymbolAddress((void**)&whi, g_wt_hi);
    cudaGetSymbolAddress((void**)&wlo, g_wt_lo);
    cudaGetSymbolAddress((void**)&tch, g_tc_hi);
    cudaGetSymbolAddress((void**)&tcl, g_tc_lo);
    cudaGetSymbolAddress((void**)&tbh, g_tb_hi);
    cudaGetSymbolAddress((void**)&tbl, g_tb_lo);

    int gemm_smem = 1024 + 2 * BUF_STRIDE;
    int prep_smem = 16 * 1028 * 4;
    cudaFuncSetAttribute(gemm3, cudaFuncAttributeMaxDynamicSharedMemorySize, gemm_smem);
    cudaFuncSetAttribute(gemm_t, cudaFuncAttributeMaxDynamicSharedMemorySize, gemm_smem);
    cudaFuncSetAttribute(prep, cudaFuncAttributeMaxDynamicSharedMemorySize, prep_smem);
    cudaFuncSetAttribute(flash_k, cudaFuncAttributeMaxDynamicSharedMemorySize, FL_SMEM);

    prep<<<PREP_FS + PREP_WS + PREP_DT, 256, prep_smem>>>(
        hs, Wc, Wb, Wx, Wout, Wdt, ahi, alo, whi, wlo);

    dim3 g3(12, MM / 128);
    gemm3<<<g3, 256, gemm_smem>>>(ahi, alo, whi, wlo, cosp, sinp,
                                  tch, tcl, tbh, tbl, px);

    kb_kernel<<<BB * NCC * HH, 256>>>(tbh, tbl, A);
    kc_kernel<<<BB * HH * 16, 256>>>(fs);

    flash_k<<<BB * NCC * HH * 2, 256, FL_SMEM>>>(tch, tcl, tbh, tbl, ahi, alo);

    dim3 gg(GN / 256, MM / 128);
    gemm_t<<<gg, 256, gemm_smem>>>(ahi, alo, whi + 3*WSZB, wlo + 3*WSZB, out);
}

// round 16
// speedup vs baseline: 1.0271x; 1.0271x over previous
#include <cuda_runtime.h>
#include <cuda_bf16.h>
#include <math.h>
#include <stdint.h>

// Problem constants (fixed by the dataset)
#define BB  2
#define LL  8192
#define DD  1024
#define HH  16
#define PP  64
#define CLc 256
#define NCC 32
#define MM  (BB*LL)   // 16384 rows

#if defined(__CUDA_ARCH_FEAT_SM103_ALL) || defined(__CUDA_ARCH_FEAT_SM100_ALL) || \
    defined(__CUDA_ARCH_FEAT_SM101_ALL) || defined(__CUDA_ARCH_SPECIFIC__)
#define HAS_TCGEN05 1
#else
#define HAS_TCGEN05 0
#endif

#define WSZB ((size_t)2 * DD * DD)   // bytes per bf16 weight matrix

// ---------------------------------------------------------------------------
// Scratch
// ---------------------------------------------------------------------------
__device__ float g_x[BB*LL*DD];     // PRE-SCALED x*dt (fp32)
__device__ float g_dt[BB*LL*HH];
__device__ float g_ac[BB*LL*HH];
__device__ float g_cdec[BB*NCC*HH];
__device__ float g_states[BB*NCC*HH*PP*PP];
__device__ float g_prev[BB*NCC*HH*PP*PP];

// c and b as per-(rowblock,head) 16KB swizzled bf16 tiles:
//   tile = (row>>7)*HH + h ; byte off = tile*16384 + swz((row&127)*128 + p*2)
__device__ __align__(1024) __nv_bfloat16 g_tc_hi[MM*DD];
__device__ __align__(1024) __nv_bfloat16 g_tc_lo[MM*DD];
__device__ __align__(1024) __nv_bfloat16 g_tb_hi[MM*DD];
__device__ __align__(1024) __nv_bfloat16 g_tb_lo[MM*DD];

// TILED bf16 GEMM operands
__device__ __align__(1024) __nv_bfloat16 g_ahi[MM*DD];
__device__ __align__(1024) __nv_bfloat16 g_alo[MM*DD];
__device__ __align__(1024) __nv_bfloat16 g_wt_hi[4][DD*DD];
__device__ __align__(1024) __nv_bfloat16 g_wt_lo[4][DD*DD];

// ---------------------------------------------------------------------------
// Helpers
// ---------------------------------------------------------------------------
__device__ __forceinline__ uint32_t smem_u32(const void* p) {
    uint32_t a;
    asm("{ .reg .u64 t; cvta.to.shared.u64 t, %1; cvt.u32.u64 %0, t; }"
        : "=r"(a) : "l"(p));
    return a;
}
__device__ __forceinline__ uint32_t swz(uint32_t off) { return off ^ ((off >> 3) & 0x70); }

__device__ __forceinline__ void split2(float v, float& hi, float& lo) {
    __nv_bfloat16 h = __float2bfloat16(v);
    hi = __bfloat162float(h);
    lo = v - hi;
}
__device__ __forceinline__ void split_pack2(float v0, float v1,
                                            uint32_t& hi2, uint32_t& lo2) {
    asm("cvt.rn.bf16x2.f32 %0, %1, %2;" : "=r"(hi2) : "f"(v1), "f"(v0));
    float h0 = __uint_as_float(hi2 << 16);
    float h1 = __uint_as_float(hi2 & 0xFFFF0000u);
    asm("cvt.rn.bf16x2.f32 %0, %1, %2;" : "=r"(lo2) : "f"(v1 - h1), "f"(v0 - h0));
}
__device__ __forceinline__ float2 unsplit2(uint32_t hv, uint32_t lv) {
    float a = __uint_as_float(hv << 16) + __uint_as_float(lv << 16);
    float b = __uint_as_float(hv & 0xFFFF0000u) + __uint_as_float(lv & 0xFFFF0000u);
    return make_float2(a, b);
}
__device__ __forceinline__ size_t cb_off(int row, int h, int p) {
    size_t tile = (size_t)((row >> 7) * HH + h);
    return (tile << 14) + swz(((uint32_t)(row & 127) << 7) + ((uint32_t)p << 1));
}
__device__ __forceinline__ float ld_cb(const char* hi, const char* lo, int row, int h, int p) {
    size_t o = cb_off(row, h, p);
    return __bfloat162float(*(const __nv_bfloat16*)(hi + o)) +
           __bfloat162float(*(const __nv_bfloat16*)(lo + o));
}
__device__ __forceinline__ uint32_t a_tile_off(int row, int k) {
    uint32_t tile = (uint32_t)(row >> 7) * 16u + (uint32_t)(k >> 6);
    return (tile << 14) + swz(((uint32_t)(row & 127) << 7) + ((uint32_t)(k & 63) << 1));
}
__device__ __forceinline__ uint32_t b_tile_off(int n, int k) {
    uint32_t tile = (uint32_t)(n >> 8) * 16u + (uint32_t)(k >> 6);
    return (tile << 15) + swz(((uint32_t)(n & 255) << 7) + ((uint32_t)(k & 63) << 1));
}

#if HAS_TCGEN05
__device__ __forceinline__ uint32_t elect_one() {
    uint32_t pred;
    asm volatile("{\n\t.reg .pred p;\n\telect.sync _|p, 0xFFFFFFFF;\n\t"
                 "selp.b32 %0, 1, 0, p;\n\t}" : "=r"(pred));
    return pred;
}
#define MBAR_INIT(a, c) \
    asm volatile("mbarrier.init.shared.b64 [%0], %1;" :: "r"(a), "r"(c) : "memory")
#define MBAR_EXPECT_TX(a, n) \
    asm volatile("mbarrier.arrive.expect_tx.shared.b64 _, [%0], %1;" :: "r"(a), "r"(n) : "memory")
#define MBAR_WAIT(a, ph) do { \
    asm volatile("{\n\t.reg .pred P1;\n\t" \
        "WL_%=:\n\t" \
        "mbarrier.try_wait.parity.acquire.cta.shared::cta.b64 P1, [%0], %1, 0x989680;\n\t" \
        "@P1 bra.uni WD_%=;\n\tbra.uni WL_%=;\n\tWD_%=:\n\t}" \
        :: "r"(a), "r"(ph) : "memory"); \
} while (0)
#define BULK_G2S(dst, src, n, mbar) \
    asm volatile("cp.async.bulk.shared::cta.global.mbarrier::complete_tx::bytes " \
                 "[%0], [%1], %2, [%3];" \
                 :: "r"(dst), "l"(src), "r"(n), "r"(mbar) : "memory")
#define TC_ALLOC(sa, n) \
    asm volatile("tcgen05.alloc.cta_group::1.sync.aligned.shared::cta.b32 [%0], %1;" \
                 :: "r"(sa), "r"(n) : "memory")
#define TC_DEALLOC(t, n) \
    asm volatile("tcgen05.dealloc.cta_group::1.sync.aligned.b32 %0, %1;" :: "r"(t), "r"(n))
#define TC_COMMIT(a) \
    asm volatile("tcgen05.commit.cta_group::1.mbarrier::arrive::one.shared::cluster.b64 [%0];" \
                 :: "r"(a) : "memory")
#define TC_FENCE_AFTER() asm volatile("tcgen05.fence::after_thread_sync;" ::: "memory")
#define TC_FENCE_BEFORE() asm volatile("tcgen05.fence::before_thread_sync;" ::: "memory")
#define TC_WAIT_LD() asm volatile("tcgen05.wait::ld.sync.aligned;" ::: "memory")
#define FENCE_ASYNC() asm volatile("fence.proxy.async.shared::cta;" ::: "memory")

__device__ __forceinline__ void mma_f16_ss(uint32_t d, uint64_t ad, uint64_t bd,
                                           uint32_t idesc, uint32_t en) {
    asm volatile("{\n\t.reg .pred p;\n\tsetp.ne.u32 p, %4, 0;\n\t"
                 "tcgen05.mma.cta_group::1.kind::f16 [%0], %1, %2, %3, {%5,%5,%5,%5}, p;\n\t}"
                 :: "r"(d), "l"(ad), "l"(bd), "r"(idesc), "r"(en), "r"(0u) : "memory");
}
__device__ __forceinline__ void ldtm32(uint32_t* r, uint32_t ta) {
    asm volatile("tcgen05.ld.sync.aligned.32x32b.x32.b32 "
        "{%0,%1,%2,%3,%4,%5,%6,%7,%8,%9,%10,%11,%12,%13,%14,%15,"
        "%16,%17,%18,%19,%20,%21,%22,%23,%24,%25,%26,%27,%28,%29,%30,%31}, [%32];"
        : "=r"(r[0]),"=r"(r[1]),"=r"(r[2]),"=r"(r[3]),"=r"(r[4]),"=r"(r[5]),"=r"(r[6]),"=r"(r[7]),
          "=r"(r[8]),"=r"(r[9]),"=r"(r[10]),"=r"(r[11]),"=r"(r[12]),"=r"(r[13]),"=r"(r[14]),"=r"(r[15]),
          "=r"(r[16]),"=r"(r[17]),"=r"(r[18]),"=r"(r[19]),"=r"(r[20]),"=r"(r[21]),"=r"(r[22]),"=r"(r[23]),
          "=r"(r[24]),"=r"(r[25]),"=r"(r[26]),"=r"(r[27]),"=r"(r[28]),"=r"(r[29]),"=r"(r[30]),"=r"(r[31])
        : "r"(ta));
}
static constexpr uint64_t DESC_BASE =
    (uint64_t(2) << 61) | (uint64_t(1) << 46) | (uint64_t(64) << 32) | (uint64_t(1) << 16);
__device__ __forceinline__ uint64_t mk_desc(uint32_t addr) {
    return DESC_BASE | ((uint64_t)(addr >> 4) & 0x3FFF);
}
#define IDESC_N(N) ((1u<<4)|(1u<<7)|(1u<<10)|(((N)/8u)<<17)|(8u<<24))
#endif  // HAS_TCGEN05

// ---------------------------------------------------------------------------
// prep: fsplit (blocks [0,8192)) + wsplit x4 ([8192,12288)) + dt2 ([12288,12800))
// ---------------------------------------------------------------------------
#define PREP_FS 8192
#define PREP_WS 4096
#define PREP_DT 512

__global__ __launch_bounds__(256) void prep(
        const float* __restrict__ hs,
        const float* __restrict__ Wc, const float* __restrict__ Wb,
        const float* __restrict__ Wx, const float* __restrict__ Wout,
        const float* __restrict__ Wdt,
        char* __restrict__ ahi, char* __restrict__ alo,
        char* __restrict__ whi, char* __restrict__ wlo) {
    extern __shared__ float sw[];
    int bid = blockIdx.x, tid = threadIdx.x;

    if (bid < PREP_FS) {
        int t = bid * 256 + tid;
        int row = t >> 7;
        int k8 = t & 127;
        const float4* p = (const float4*)(hs + ((size_t)row << 10) + (k8 << 3));
        float4 v0 = p[0], v1 = p[1];
        uint4 hv, lv;
        split_pack2(v0.x, v0.y, hv.x, lv.x);
        split_pack2(v0.z, v0.w, hv.y, lv.y);
        split_pack2(v1.x, v1.y, hv.z, lv.z);
        split_pack2(v1.z, v1.w, hv.w, lv.w);
        uint32_t tile = (uint32_t)(row >> 7) * 16u + (uint32_t)(k8 >> 3);
        uint32_t off = (tile << 14) + swz(((uint32_t)(row & 127) << 7) + ((uint32_t)(k8 & 7) << 4));
        *(uint4*)(ahi + off) = hv;
        *(uint4*)(alo + off) = lv;
    } else if (bid < PREP_FS + PREP_WS) {
        int q = bid - PREP_FS;
        int m = q >> 10;
        const float* W = (m == 0) ? Wc : (m == 1) ? Wb : (m == 2) ? Wx : Wout;
        char* Thi = whi + (size_t)m * WSZB;
        char* Tlo = wlo + (size_t)m * WSZB;
        int qq = q & 1023;
        int bx = (qq & 31) * 32, by = (qq >> 5) * 32;
        float (*t)[33] = (float(*)[33])sw;
        int x = tid & 31, y = tid >> 5;
#pragma unroll
        for (int j = 0; j < 4; j++)
            t[y + j*8][x] = W[(size_t)(by + y + j*8) * DD + bx + x];
        __syncthreads();
#pragma unroll
        for (int j = 0; j < 4; j++) {
            float v = t[x][y + j*8];
            float h, l;
            split2(v, h, l);
            int n = bx + y + j*8, k = by + x;
            uint32_t off = b_tile_off(n, k);
            *(__nv_bfloat16*)(Thi + off) = __float2bfloat16(h);
            *(__nv_bfloat16*)(Tlo + off) = __float2bfloat16(l);
        }
    } else {
        int blk = bid - PREP_FS - PREP_WS;
        for (int i = tid; i < 16384; i += 256)
            sw[(i & 15) * 1028 + (i >> 4)] = Wdt[i];
        __syncthreads();
        int w = tid >> 5, l = tid & 31;
        int row0 = blk * 32 + w * 4;
        float acc[4][16];
#pragma unroll
        for (int r = 0; r < 4; r++)
#pragma unroll
            for (int n = 0; n < 16; n++) acc[r][n] = 0.f;
#pragma unroll
        for (int it = 0; it < 8; it++) {
            int k0 = it * 128 + l * 4;
            float4 h[4];
#pragma unroll
            for (int r = 0; r < 4; r++)
                h[r] = *(const float4*)&hs[(size_t)(row0 + r) * DD + k0];
#pragma unroll
            for (int n = 0; n < 16; n++) {
                float4 wv = *(const float4*)&sw[n * 1028 + k0];
#pragma unroll
                for (int r = 0; r < 4; r++)
                    acc[r][n] += h[r].x*wv.x + h[r].y*wv.y + h[r].z*wv.z + h[r].w*wv.w;
            }
        }
#pragma unroll
        for (int off = 16; off; off >>= 1)
#pragma unroll
            for (int r = 0; r < 4; r++)
#pragma unroll
                for (int n = 0; n < 16; n++)
                    acc[r][n] += __shfl_xor_sync(0xFFFFFFFFu, acc[r][n], off);
        if (l == 0) {
#pragma unroll
            for (int r = 0; r < 4; r++)
#pragma unroll
                for (int n = 0; n < 16; n++) {
                    float s = acc[r][n];
                    g_dt[(row0 + r) * HH + n] = fmaxf(s, 0.f) + log1pf(expf(-fabsf(s)));
                }
        }
    }
}

// ---------------------------------------------------------------------------
// GEMM common constants
// ---------------------------------------------------------------------------
#define GK 1024
#define GN 1024
#define NCHUNK 16
#define BUF_STRIDE 98304
#define GIDESC ((1u<<4)|(1u<<7)|(1u<<10)|((256u/8)<<17)|((128u/16)<<24))

// ---------------------------------------------------------------------------
// gemm3: merged projection GEMM. grid=(12,128). mode=bn>>2: 0=c 1=b 2=x.
// ---------------------------------------------------------------------------
__global__ __launch_bounds__(256, 1) void gemm3(
        const char* __restrict__ Ahi, const char* __restrict__ Alo,
        const char* __restrict__ Whi, const char* __restrict__ Wlo,
        const float* __restrict__ cosp, const float* __restrict__ sinp,
        char* __restrict__ tch, char* __restrict__ tcl,
        char* __restrict__ tbh, char* __restrict__ tbl,
        float* __restrict__ px) {
    extern __shared__ char sm[];
    int tid = threadIdx.x;
    int wid = tid >> 5, lid = tid & 31;
    int bn = blockIdx.x, bm = blockIdx.y;
    int mode = bn >> 2;
#if HAS_TCGEN05
    uint32_t sbase = smem_u32(sm);
    if (tid == 0) {
        MBAR_INIT(sbase + 8, 1);  MBAR_INIT(sbase + 16, 1);
        MBAR_INIT(sbase + 24, 1); MBAR_INIT(sbase + 32, 1);
    }
    if (wid == 0) TC_ALLOC(sbase, 256);
    __syncthreads();
    uint32_t tmem;
    asm volatile("ld.shared.b32 %0, [%1];" : "=r"(tmem) : "r"(sbase));

    if (wid == 0 && elect_one()) {
        auto load = [&](int chunk, int b) {
            uint32_t mb = sbase + 8 + (uint32_t)b * 8;
            MBAR_EXPECT_TX(mb, 98304u);
            uint32_t d = sbase + 1024u + (uint32_t)b * BUF_STRIDE;
            size_t ao = ((size_t)bm * 16 + chunk) << 14;
            size_t bo = ((size_t)bn * 16 + chunk) << 15;
            BULK_G2S(d,          Ahi + ao, 16384u, mb);
            BULK_G2S(d + 16384,  Alo + ao, 16384u, mb);
            BULK_G2S(d + 32768,  Whi + bo, 32768u, mb);
            BULK_G2S(d + 65536,  Wlo + bo, 32768u, mb);
        };
        load(0, 0);
        load(1, 1);
        int f0 = 0, f1 = 0, e0 = 0, e1 = 0;
        for (int k = 0; k < NCHUNK; k++) {
            int b = k & 1;
            if (b == 0) { MBAR_WAIT(sbase + 8, f0);  f0 ^= 1; }
            else        { MBAR_WAIT(sbase + 16, f1); f1 ^= 1; }
            uint32_t boff = sbase + 1024u + (uint32_t)b * BUF_STRIDE;
            uint64_t dah = mk_desc(boff);
            uint64_t dal = mk_desc(boff + 16384);
            uint64_t dbh = mk_desc(boff + 32768);
            uint64_t dbl = mk_desc(boff + 65536);
#pragma unroll
            for (int ks = 0; ks < 4; ks++) {
                mma_f16_ss(tmem, dah + ks*2, dbh + ks*2, GIDESC,
                           (k == 0 && ks == 0) ? 0u : 1u);
                mma_f16_ss(tmem, dah + ks*2, dbl + ks*2, GIDESC, 1u);
                mma_f16_ss(tmem, dal + ks*2, dbh + ks*2, GIDESC, 1u);
            }
            TC_COMMIT(sbase + 24 + (uint32_t)b * 8);
            if (k + 2 < NCHUNK) {
                if (b == 0) { MBAR_WAIT(sbase + 24, e0); e0 ^= 1; }
                else        { MBAR_WAIT(sbase + 32, e1); e1 ^= 1; }
                load(k + 2, b);
            }
        }
        MBAR_WAIT(sbase + 24, e0);
        MBAR_WAIT(sbase + 32, e1);
    }
    __syncthreads();
    TC_FENCE_AFTER();

    {
        int sub = wid & 3, grp = wid >> 2;
        int row = bm * 128 + sub * 32 + lid;
        if (mode < 2) {
            char* Thi = (mode == 0) ? tch : tbh;
            char* Tlo = (mode == 0) ? tcl : tbl;
            const float* cr = cosp + (size_t)row * 64;
            const float* sr = sinp + (size_t)row * 64;
            uint32_t rb = (uint32_t)(row & 127) * 128;
#pragma unroll
            for (int cb2 = 0; cb2 < 2; cb2++) {
                int head64 = (grp * 2 + cb2) * 64;
                uint32_t r0[32], r1[32];
                ldtm32(r0, tmem + head64);      TC_WAIT_LD();
                ldtm32(r1, tmem + head64 + 32); TC_WAIT_LD();
                int hidx = (bn & 3) * 4 + grp * 2 + cb2;
                size_t tb = ((size_t)((row >> 7) * HH + hidx)) << 14;
#pragma unroll
                for (int j = 0; j < 32; j += 4) {
                    float4 c1 = *(const float4*)(cr + j);
                    float4 s1 = *(const float4*)(sr + j);
                    float4 c2 = *(const float4*)(cr + j + 32);
                    float4 s2 = *(const float4*)(sr + j + 32);
                    float a0 = __uint_as_float(r0[j]),   a1 = __uint_as_float(r0[j+1]);
                    float a2 = __uint_as_float(r0[j+2]), a3 = __uint_as_float(r0[j+3]);
                    float q0 = __uint_as_float(r1[j]),   q1 = __uint_as_float(r1[j+1]);
                    float q2 = __uint_as_float(r1[j+2]), q3 = __uint_as_float(r1[j+3]);
                    uint2 h1, l1, h2, l2;
                    split_pack2(a0*c1.x - q0*s1.x, a1*c1.y - q1*s1.y, h1.x, l1.x);
                    split_pack2(a2*c1.z - q2*s1.z, a3*c1.w - q3*s1.w, h1.y, l1.y);
                    split_pack2(q0*c2.x + a0*s2.x, q1*c2.y + a1*s2.y, h2.x, l2.x);
                    split_pack2(q2*c2.z + a2*s2.z, q3*c2.w + a3*s2.w, h2.y, l2.y);
                    uint32_t o1 = swz(rb + j * 2);
                    uint32_t o2 = swz(rb + 64 + j * 2);
                    *(uint2*)(Thi + tb + o1) = h1;
                    *(uint2*)(Tlo + tb + o1) = l1;
                    *(uint2*)(Thi + tb + o2) = h2;
                    *(uint2*)(Tlo + tb + o2) = l2;
                }
            }
        } else {
            int bnc = (bn & 3) * 256;
            float* crow = px + (size_t)row * GN + bnc;
#pragma unroll
            for (int cb2 = 0; cb2 < 2; cb2++) {
                int head64 = (grp * 2 + cb2) * 64;
                uint32_t r0[32], r1[32];
                ldtm32(r0, tmem + head64);      TC_WAIT_LD();
                ldtm32(r1, tmem + head64 + 32); TC_WAIT_LD();
                int hidx = (bnc >> 6) + grp * 2 + cb2;
                float dtv = g_dt[row * HH + hidx];
#pragma unroll
                for (int j = 0; j < 32; j += 4) {
                    float4 o1 = make_float4(__uint_as_float(r0[j])   * dtv,
                                            __uint_as_float(r0[j+1]) * dtv,
                                            __uint_as_float(r0[j+2]) * dtv,
                                            __uint_as_float(r0[j+3]) * dtv);
                    float4 o2 = make_float4(__uint_as_float(r1[j])   * dtv,
                                            __uint_as_float(r1[j+1]) * dtv,
                                            __uint_as_float(r1[j+2]) * dtv,
                                            __uint_as_float(r1[j+3]) * dtv);
                    *(float4*)(crow + head64 + j)      = o1;
                    *(float4*)(crow + head64 + 32 + j) = o2;
                }
            }
        }
        TC_FENCE_BEFORE();
    }
    __syncthreads();
    if (wid == 0) TC_DEALLOC(tmem, 256);
#else
    // CUDA-core fallback
    int tx = tid & 15, ty = tid >> 4;
    int bmr = bm * 128;
    float* sA = (float*)sm;
    float* sB = (float*)(sm + 8192);
    float* stg = (float*)(sm + 16384);
    auto rdA = [&](const char* p, int row, int k) {
        return __bfloat162float(*(const __nv_bfloat16*)(p + a_tile_off(row, k)));
    };
    auto rdBW = [&](const char* p, int gn, int k) {
        uint32_t tile = (uint32_t)(gn >> 8) * 16u + (uint32_t)(k >> 6);
        uint32_t off = (tile << 15) + swz(((uint32_t)(gn & 255) << 7) + ((uint32_t)(k & 63) << 1));
        return __bfloat162float(*(const __nv_bfloat16*)(p + off));
    };
    for (int half = 0; half < 2; half++) {
        int bn2 = bn * 256 + half * 128;
        float acc[8][8];
#pragma unroll
        for (int i = 0; i < 8; i++)
#pragma unroll
            for (int j = 0; j < 8; j++) acc[i][j] = 0.f;
        for (int k0 = 0; k0 < GK; k0 += 16) {
            for (int i = tid; i < 2048; i += 256) {
                int r = i >> 4, kk = i & 15;
                sA[kk*128 + r] = rdA(Ahi, bmr + r, k0 + kk) + rdA(Alo, bmr + r, k0 + kk);
                sB[kk*128 + r] = rdBW(Whi, bn2 + r, k0 + kk) + rdBW(Wlo, bn2 + r, k0 + kk);
            }
            __syncthreads();
#pragma unroll
            for (int kk = 0; kk < 16; kk++) {
                float a[8], b[8];
#pragma unroll
                for (int i = 0; i < 4; i++) {
                    a[i] = sA[kk*128 + ty*4 + i];
                    a[i+4] = sA[kk*128 + 64 + ty*4 + i];
                    b[i] = sB[kk*128 + tx*4 + i];
                    b[i+4] = sB[kk*128 + 64 + tx*4 + i];
                }
#pragma unroll
                for (int i = 0; i < 8; i++)
#pragma unroll
                    for (int j = 0; j < 8; j++) acc[i][j] += a[i] * b[j];
            }
            __syncthreads();
        }
#pragma unroll
        for (int i = 0; i < 8; i++) {
            int rl = (i < 4) ? (ty*4 + i) : (64 + ty*4 + i - 4);
#pragma unroll
            for (int j = 0; j < 8; j++) {
                int cl = (j < 4) ? (tx*4 + j) : (64 + tx*4 + j - 4);
                stg[rl * 128 + cl] = acc[i][j];
            }
        }
        __syncthreads();
        if (mode < 2) {
            char* Thi = (mode == 0) ? tch : tbh;
            char* Tlo = (mode == 0) ? tcl : tbl;
            for (int u = tid; u < 128 * 64; u += 256) {
                int rr = u >> 6, ps = u & 63;
                int head = ps >> 5, p = ps & 31;
                int row = bmr + rr;
                float a = stg[rr*128 + head*64 + p];
                float q = stg[rr*128 + head*64 + p + 32];
                float c1 = cosp[row*64 + p],      s1 = sinp[row*64 + p];
                float c2 = cosp[row*64 + p + 32], s2 = sinp[row*64 + p + 32];
                float v1 = a * c1 - q * s1;
                float v2 = q * c2 + a * s2;
                int hidx = (bn & 3) * 4 + half * 2 + head;
                float hh, llv;
                split2(v1, hh, llv);
                size_t o = cb_off(row, hidx, p);
                *(__nv_bfloat16*)(Thi + o) = __float2bfloat16(hh);
                *(__nv_bfloat16*)(Tlo + o) = __float2bfloat16(llv);
                split2(v2, hh, llv);
                o = cb_off(row, hidx, p + 32);
                *(__nv_bfloat16*)(Thi + o) = __float2bfloat16(hh);
                *(__nv_bfloat16*)(Tlo + o) = __float2bfloat16(llv);
            }
        } else {
            int bnc = (bn & 3) * 256 + half * 128;
            for (int u = tid; u < 128 * 128; u += 256) {
                int rr = u >> 7, cl = u & 127;
                int row = bmr + rr;
                int hidx = (bnc + cl) >> 6;
                px[(size_t)row * GN + bnc + cl] = stg[rr*128 + cl] * g_dt[row * HH + hidx];
            }
        }
        __syncthreads();
    }
#endif
}

// ---------------------------------------------------------------------------
// gemm_t: plain GEMM (final Wout). grid=(4,128).
// ---------------------------------------------------------------------------
__global__ __launch_bounds__(256, 1) void gemm_t(
        const char* __restrict__ Ahi, const char* __restrict__ Alo,
        const char* __restrict__ Bhi, const char* __restrict__ Blo,
        float* __restrict__ C) {
    extern __shared__ char sm[];
#if HAS_TCGEN05
    uint32_t sbase = smem_u32(sm);
    int tid = threadIdx.x;
    int wid = tid >> 5, lid = tid & 31;
    int bn = blockIdx.x, bm = blockIdx.y;

    if (tid == 0) {
        MBAR_INIT(sbase + 8, 1);  MBAR_INIT(sbase + 16, 1);
        MBAR_INIT(sbase + 24, 1); MBAR_INIT(sbase + 32, 1);
    }
    if (wid == 0) TC_ALLOC(sbase, 256);
    __syncthreads();
    uint32_t tmem;
    asm volatile("ld.shared.b32 %0, [%1];" : "=r"(tmem) : "r"(sbase));

    if (wid == 0 && elect_one()) {
        auto load = [&](int chunk, int b) {
            uint32_t mb = sbase + 8 + (uint32_t)b * 8;
            MBAR_EXPECT_TX(mb, 98304u);
            uint32_t d = sbase + 1024u + (uint32_t)b * BUF_STRIDE;
            size_t ao = ((size_t)bm * 16 + chunk) << 14;
            size_t bo = ((size_t)bn * 16 + chunk) << 15;
            BULK_G2S(d,          Ahi + ao, 16384u, mb);
            BULK_G2S(d + 16384,  Alo + ao, 16384u, mb);
            BULK_G2S(d + 32768,  Bhi + bo, 32768u, mb);
            BULK_G2S(d + 65536,  Blo + bo, 32768u, mb);
        };
        load(0, 0);
        load(1, 1);
        int f0 = 0, f1 = 0, e0 = 0, e1 = 0;
        for (int k = 0; k < NCHUNK; k++) {
            int b = k & 1;
            if (b == 0) { MBAR_WAIT(sbase + 8, f0);  f0 ^= 1; }
            else        { MBAR_WAIT(sbase + 16, f1); f1 ^= 1; }
            uint32_t boff = sbase + 1024u + (uint32_t)b * BUF_STRIDE;
            uint64_t dah = mk_desc(boff);
            uint64_t dal = mk_desc(boff + 16384);
            uint64_t dbh = mk_desc(boff + 32768);
            uint64_t dbl = mk_desc(boff + 65536);
#pragma unroll
            for (int ks = 0; ks < 4; ks++) {
                mma_f16_ss(tmem, dah + ks*2, dbh + ks*2, GIDESC,
                           (k == 0 && ks == 0) ? 0u : 1u);
                mma_f16_ss(tmem, dah + ks*2, dbl + ks*2, GIDESC, 1u);
                mma_f16_ss(tmem, dal + ks*2, dbh + ks*2, GIDESC, 1u);
            }
            TC_COMMIT(sbase + 24 + (uint32_t)b * 8);
            if (k + 2 < NCHUNK) {
                if (b == 0) { MBAR_WAIT(sbase + 24, e0); e0 ^= 1; }
                else        { MBAR_WAIT(sbase + 32, e1); e1 ^= 1; }
                load(k + 2, b);
            }
        }
        MBAR_WAIT(sbase + 24, e0);
        MBAR_WAIT(sbase + 32, e1);
    }
    __syncthreads();
    TC_FENCE_AFTER();

    {
        int sub = wid & 3, grp = wid >> 2;
        int row = bm * 128 + sub * 32 + lid;
        float* crow = C + (size_t)row * GN + bn * 256;
#pragma unroll
        for (int cb = grp * 4; cb < grp * 4 + 4; cb++) {
            uint32_t r[32];
            ldtm32(r, tmem + cb * 32);
            TC_WAIT_LD();
#pragma unroll
            for (int j = 0; j < 8; j++) {
                float4 v = make_float4(__uint_as_float(r[j*4]), __uint_as_float(r[j*4+1]),
                                       __uint_as_float(r[j*4+2]), __uint_as_float(r[j*4+3]));
                *(float4*)(crow + cb * 32 + j * 4) = v;
            }
        }
        TC_FENCE_BEFORE();
    }
    __syncthreads();
    if (wid == 0) TC_DEALLOC(tmem, 256);
#else
    int tid = threadIdx.x;
    int tx = tid & 15, ty = tid >> 4;
    int bn = blockIdx.x * 256, bm = blockIdx.y * 128;
    float* sA = (float*)sm;
    float* sB = (float*)(sm + 8192);
    auto rdA = [&](const char* p, int row, int k) {
        return __bfloat162float(*(const __nv_bfloat16*)(p + a_tile_off(row, k)));
    };
    auto rdB = [&](const char* p, int n, int k) {
        return __bfloat162float(*(const __nv_bfloat16*)(p + b_tile_off(n, k)));
    };
    for (int half = 0; half < 2; half++) {
        int bn2 = bn + half * 128;
        float acc[8][8];
#pragma unroll
        for (int i = 0; i < 8; i++)
#pragma unroll
            for (int j = 0; j < 8; j++) acc[i][j] = 0.f;
        for (int k0 = 0; k0 < GK; k0 += 16) {
            for (int i = tid; i < 2048; i += 256) {
                int r = i >> 4, kk = i & 15;
                sA[kk*128 + r] = rdA(Ahi, bm + r, k0 + kk) + rdA(Alo, bm + r, k0 + kk);
                sB[kk*128 + r] = rdB(Bhi, bn2 + r, k0 + kk) + rdB(Blo, bn2 + r, k0 + kk);
            }
            __syncthreads();
#pragma unroll
            for (int kk = 0; kk < 16; kk++) {
                float a[8], b[8];
#pragma unroll
                for (int i = 0; i < 4; i++) {
                    a[i] = sA[kk*128 + ty*4 + i];
                    a[i+4] = sA[kk*128 + 64 + ty*4 + i];
                    b[i] = sB[kk*128 + tx*4 + i];
                    b[i+4] = sB[kk*128 + 64 + tx*4 + i];
                }
#pragma unroll
                for (int i = 0; i < 8; i++)
#pragma unroll
                    for (int j = 0; j < 8; j++) acc[i][j] += a[i] * b[j];
            }
            __syncthreads();
        }
#pragma unroll
        for (int i = 0; i < 8; i++) {
            int row = bm + ((i < 4) ? (ty*4 + i) : (64 + ty*4 + i - 4));
#pragma unroll
            for (int j = 0; j < 8; j++) {
                int col = bn2 + ((j < 4) ? (tx*4 + j) : (64 + tx*4 + j - 4));
                C[(size_t)row * GN + col] = acc[i][j];
            }
        }
        __syncthreads();
    }
#endif
}

// ---------------------------------------------------------------------------
// kb: fused acum (per-chunk cumsum of dt*A) + chunk states.
// ---------------------------------------------------------------------------
__global__ __launch_bounds__(256) void kb_kernel(const char* __restrict__ tbh,
                                                 const char* __restrict__ tbl,
                                                 const float* __restrict__ A) {
    __shared__ float sX[4096];
    __shared__ float sB[4096];
    __shared__ float sac[256];
    int bid = blockIdx.x;
    int h = bid & 15, c = (bid >> 4) & 31, b = bid >> 9;
    int tid = threadIdx.x, tx = tid & 15, ty = tid >> 4;
    int chunk_row = b * LL + c * CLc;

    sac[tid] = g_dt[(chunk_row + tid) * HH + h] * A[h];
    __syncthreads();
    for (int off = 1; off < 256; off <<= 1) {
        float u = (tid >= off) ? sac[tid - off] : 0.f;
        __syncthreads();
        sac[tid] += u;
        __syncthreads();
    }
    g_ac[(chunk_row + tid) * HH + h] = sac[tid];
    if (tid == 255) g_cdec[bid] = expf(sac[255]);
    __syncthreads();
    float aclast = sac[255];

    float acc[4][4];
#pragma unroll
    for (int i = 0; i < 4; i++)
#pragma unroll
        for (int j = 0; j < 4; j++) acc[i][j] = 0.f;

    for (int ltile = 0; ltile < 4; ltile++) {
        int r0 = chunk_row + ltile * 64;
#pragma unroll
        for (int t = 0; t < 2; t++) {
            int u = tid + t * 256;
            int rr = u >> 3, p8 = (u & 7) * 8;
            int row = r0 + rr;
            size_t to = (((size_t)((row >> 7) * HH + h)) << 14) +
                        swz(((uint32_t)(row & 127) << 7) + ((uint32_t)p8 << 1));
            uint4 hv = *(const uint4*)(tbh + to);
            uint4 lv = *(const uint4*)(tbl + to);
            float w = __expf(aclast - sac[ltile * 64 + rr]);
            float2 f0 = unsplit2(hv.x, lv.x);
            float2 f1 = unsplit2(hv.y, lv.y);
            float2 f2 = unsplit2(hv.z, lv.z);
            float2 f3 = unsplit2(hv.w, lv.w);
            *(float4*)&sB[rr*64 + p8]     = make_float4(f0.x*w, f0.y*w, f1.x*w, f1.y*w);
            *(float4*)&sB[rr*64 + p8 + 4] = make_float4(f2.x*w, f2.y*w, f3.x*w, f3.y*w);
            const float* xx = g_x + (size_t)row * DD + h * 64 + p8;
            *(float4*)&sX[rr*64 + p8]     = *(const float4*)xx;
            *(float4*)&sX[rr*64 + p8 + 4] = *(const float4*)(xx + 4);
        }
        __syncthreads();
#pragma unroll 4
        for (int l = 0; l < 64; l++) {
            float xv[4], bv[4];
#pragma unroll
            for (int i = 0; i < 4; i++) xv[i] = sX[l * 64 + ty * 4 + i];
#pragma unroll
            for (int j = 0; j < 4; j++) bv[j] = sB[l * 64 + tx * 4 + j];
#pragma unroll
            for (int i = 0; i < 4; i++)
#pragma unroll
                for (int j = 0; j < 4; j++) acc[i][j] += xv[i] * bv[j];
        }
        __syncthreads();
    }
    int sb = ((b * NCC + c) * HH + h) * 4096;
#pragma unroll
    for (int i = 0; i < 4; i++) {
        float4 v = make_float4(acc[i][0], acc[i][1], acc[i][2], acc[i][3]);
        *(float4*)&g_states[sb + (ty * 4 + i) * 64 + tx * 4] = v;
    }
}

// ---------------------------------------------------------------------------
// kc: sequential chunk scan, one element per thread. grid = BB*HH*16.
// ---------------------------------------------------------------------------
__global__ __launch_bounds__(256) void kc_kernel(float* __restrict__ fs) {
    int bid = blockIdx.x;
    int ks = bid & 15;
    int h = (bid >> 4) & 15;
    int b = bid >> 8;
    int e = ks * 256 + threadIdx.x;
    int bh = b * NCC * HH + h;
    float st = 0.f;
#pragma unroll 4
    for (int c = 0; c < NCC; c++) {
        float dec = g_cdec[(b * NCC + c) * HH + h];
        int base = (bh + c * HH) * 4096 + e;
        g_prev[base] = st;
        st = st * dec + g_states[base];
    }
    fs[(b * HH + h) * 4096 + e] = st;
}

// ---------------------------------------------------------------------------
// Flash kernel: C/B via cp.async.bulk; X/P elementwise fills. (R13 structure)
// ---------------------------------------------------------------------------
#define FL_SMEM 183296
#define FO_AC   64
#define FO_EC   1088
#define FO_CHI  3072
#define FO_CLO  19456
#define FO_BHI  35840
#define FO_BLO  68608
#define FO_XHI  101376
#define FO_XLO  134144
#define FO_PHI  166912
#define FO_PLO  175104

__global__ __launch_bounds__(256, 1) void flash_k(const char* __restrict__ tch,
                                                  const char* __restrict__ tcl,
                                                  const char* __restrict__ tbh,
                                                  const char* __restrict__ tbl,
                                                  char* __restrict__ yhi,
                                                  char* __restrict__ ylo) {
    extern __shared__ char sm[];
    int tid = threadIdx.x, wid = tid >> 5, lid = tid & 31;
    int bid = blockIdx.x;
    int half = bid & 1, h = (bid >> 1) & 15, c = (bid >> 5) & 31, b = bid >> 10;
    int chunk_row = b * LL + c * CLc;
    int l0g = half * 128;
    int SL = half ? 256 : 128;
    float* acs = (float*)(sm + FO_AC);
    float* ecol = (float*)(sm + FO_EC);

#if HAS_TCGEN05
    uint32_t sbase = smem_u32(sm);
    int nsl = SL / 128;
    if (tid == 0) {
        MBAR_INIT(sbase + 8, 1);  MBAR_INIT(sbase + 16, 1);
        MBAR_INIT(sbase + 24, 1); MBAR_INIT(sbase + 32, 1);
        MBAR_INIT(sbase + 40, 1);
    }
    if (wid == 0) TC_ALLOC(sbase, 512);
    __syncthreads();
    uint32_t tmem;
    asm volatile("ld.shared.b32 %0, [%1];" : "=r"(tmem) : "r"(sbase));

    if (tid == 0) {
        uint32_t nbytes = 32768u * (uint32_t)(1 + nsl);
        MBAR_EXPECT_TX(sbase + 40, nbytes);
        size_t ct = ((size_t)(((chunk_row + l0g) >> 7) * HH + h)) << 14;
        BULK_G2S(sbase + FO_CHI, tch + ct, 16384u, sbase + 40);
        BULK_G2S(sbase + FO_CLO, tcl + ct, 16384u, sbase + 40);
        for (int i = 0; i < nsl; i++) {
            size_t bt = ((size_t)(((chunk_row >> 7) + i) * HH + h)) << 14;
            BULK_G2S(sbase + FO_BHI + (uint32_t)i * 16384u, tbh + bt, 16384u, sbase + 40);
            BULK_G2S(sbase + FO_BLO + (uint32_t)i * 16384u, tbl + bt, 16384u, sbase + 40);
        }
    }

    acs[tid] = g_ac[(chunk_row + tid) * HH + h];
    __syncthreads();
    ecol[tid] = __expf(acs[tid & ~31] - acs[tid]);

    for (int t = 0; t < SL/16; t++) {
        int u = tid + t * 256;
        int p = u & 63, sg = u >> 6;
        int s0 = sg * 4;
        float xv[4];
#pragma unroll
        for (int i = 0; i < 4; i++)
            xv[i] = g_x[(size_t)(chunk_row + s0 + i) * DD + h*64 + p];
        uint2 hv, lv;
        split_pack2(xv[0], xv[1], hv.x, lv.x);
        split_pack2(xv[2], xv[3], hv.y, lv.y);
        uint32_t off = swz((uint32_t)(((p>>3) + (s0>>6)*8)*1024 + (p&7)*128 + (s0&63)*2));
        *(uint2*)(sm + FO_XHI + off) = hv;
        *(uint2*)(sm + FO_XLO + off) = lv;
    }
    {
        int pbase = ((b * NCC + c) * HH + h) * 4096;
#pragma unroll
        for (int t = 0; t < 4; t++) {
            int u = tid + t * 256;
            int p = u >> 4, n4 = (u & 15) * 4;
            float4 v = *(const float4*)(g_prev + pbase + p*64 + n4);
            uint2 hv, lv;
            split_pack2(v.x, v.y, hv.x, lv.x);
            split_pack2(v.z, v.w, hv.y, lv.y);
            uint32_t off = swz((uint32_t)(p*128 + n4*2));
            *(uint2*)(sm + FO_PHI + off) = hv;
            *(uint2*)(sm + FO_PLO + off) = lv;
        }
    }
    FENCE_ASYNC();
    __syncthreads();

    if (wid == 0 && elect_one()) {
        MBAR_WAIT(sbase + 40, 0);
        uint64_t dCh = mk_desc(sbase + FO_CHI), dCl = mk_desc(sbase + FO_CLO);
        uint64_t dBh = mk_desc(sbase + FO_BHI), dBl = mk_desc(sbase + FO_BLO);
        uint32_t id1 = (SL == 128) ? IDESC_N(128) : IDESC_N(256);
#pragma unroll
        for (int ks = 0; ks < 4; ks++) {
            mma_f16_ss(tmem, dCh + ks*2, dBh + ks*2, id1, ks > 0);
            mma_f16_ss(tmem, dCh + ks*2, dBl + ks*2, id1, 1);
            mma_f16_ss(tmem, dCl + ks*2, dBh + ks*2, id1, 1);
        }
        TC_COMMIT(sbase + 8);
        uint64_t dPh = mk_desc(sbase + FO_PHI), dPl = mk_desc(sbase + FO_PLO);
        uint32_t id64 = IDESC_N(64);
#pragma unroll
        for (int ks = 0; ks < 4; ks++) {
            mma_f16_ss(tmem + 320, dCh + ks*2, dPh + ks*2, id64, ks > 0);
            mma_f16_ss(tmem + 320, dCh + ks*2, dPl + ks*2, id64, 1);
            mma_f16_ss(tmem + 320, dCl + ks*2, dPh + ks*2, id64, 1);
        }
        TC_COMMIT(sbase + 16);
    }
    MBAR_WAIT(sbase + 8, 0);
    TC_FENCE_AFTER();

    int sub = wid & 3, grp = wid >> 2;
    int lrow = sub * 32 + lid;
    float acl = acs[l0g + lrow];

    float erow[8];
#pragma unroll
    for (int j = 0; j < 8; j++) erow[j] = __expf(acl - acs[j * 32]);

    for (int sl = 0; sl < nsl; sl++) {
        if (sl == 1) MBAR_WAIT(sbase + 24, 0);
#pragma unroll
        for (int rd = grp; rd < 4; rd += 2) {
            uint32_t r[32];
            ldtm32(r, tmem + sl*128 + rd*32);
            TC_WAIT_LD();
            int colbase = sl*128 + rd*32;
            float er = erow[colbase >> 5];
#pragma unroll
            for (int j = 0; j < 32; j += 4) {
                float vv[4];
#pragma unroll
                for (int i = 0; i < 4; i++) {
                    int cg = colbase + j + i;
                    float v = __uint_as_float(r[j+i]) * er * ecol[cg];
                    vv[i] = (cg <= l0g + lrow) ? v : 0.f;
                }
                uint2 hv, lv;
                split_pack2(vv[0], vv[1], hv.x, lv.x);
                split_pack2(vv[2], vv[3], hv.y, lv.y);
                int sIn = rd*32 + j;
                uint32_t off = swz((uint32_t)(((lrow>>3) + (sIn>>6)*16)*1024
                                              + (lrow&7)*128 + (sIn&63)*2));
                *(uint2*)(sm + FO_BHI + off) = hv;
                *(uint2*)(sm + FO_BLO + off) = lv;
            }
        }
        FENCE_ASYNC();
        __syncthreads();
        if (wid == 0 && elect_one()) {
            uint64_t dSh = mk_desc(sbase + FO_BHI), dSl = mk_desc(sbase + FO_BLO);
            uint64_t dXh = mk_desc(sbase + FO_XHI), dXl = mk_desc(sbase + FO_XLO);
            uint32_t id64 = IDESC_N(64);
#pragma unroll
            for (int ks2 = 0; ks2 < 8; ks2++) {
                int ksg = sl*8 + ks2;
                uint64_t ao = (uint64_t)((ks2 >> 2)*1024 + (ks2 & 3)*2);
                uint64_t bo = (uint64_t)((ksg >> 2)*512 + (ksg & 3)*2);
                mma_f16_ss(tmem + 256, dSh + ao, dXh + bo, id64,
                           !(sl == 0 && ks2 == 0));
                mma_f16_ss(tmem + 256, dSh + ao, dXl + bo, id64, 1);
                mma_f16_ss(tmem + 256, dSl + ao, dXh + bo, id64, 1);
            }
            TC_COMMIT(sbase + 24 + (uint32_t)sl * 8);
        }
    }
    MBAR_WAIT(sbase + 24 + (uint32_t)(nsl - 1) * 8, 0);
    MBAR_WAIT(sbase + 16, 0);
    TC_FENCE_AFTER();

    {
        int row = chunk_row + l0g + lrow;
        uint32_t tile = (uint32_t)(row >> 7) * 16u + (uint32_t)h;
        char* dhi = yhi + ((size_t)tile << 14);
        char* dlo = ylo + ((size_t)tile << 14);
        float e = __expf(acl);
        uint32_t y1[32], y2[32];
        ldtm32(y1, tmem + 256 + grp*32);
        ldtm32(y2, tmem + 320 + grp*32);
        TC_WAIT_LD();
#pragma unroll
        for (int j = 0; j < 32; j += 4) {
            float vv[4];
#pragma unroll
            for (int i = 0; i < 4; i++)
                vv[i] = __uint_as_float(y1[j+i]) + e * __uint_as_float(y2[j+i]);
            uint2 hv, lv;
            split_pack2(vv[0], vv[1], hv.x, lv.x);
            split_pack2(vv[2], vv[3], hv.y, lv.y);
            uint32_t off = swz((uint32_t)((row & 127)*128 + (grp*32 + j)*2));
            *(uint2*)(dhi + off) = hv;
            *(uint2*)(dlo + off) = lv;
        }
        TC_FENCE_BEFORE();
    }
    __syncthreads();
    if (wid == 0) TC_DEALLOC(tmem, 512);
#else
    // CUDA-core fallback
    float* sC = (float*)(sm + FO_CHI);
    float* sS = (float*)(sm + FO_BHI);
    float* sB = (float*)(sm + FO_BLO);
    float* sX = (float*)(sm + FO_XHI);
    float* sP = (float*)(sm + FO_XLO);
    int tx = tid & 15, ty = tid >> 4;

    acs[tid] = g_ac[(chunk_row + tid) * HH + h];
    for (int t = 0; t < 16; t++) {
        int pr = tid + t * 256;
        int rr = pr >> 5, pp = pr & 31;
        int row = chunk_row + l0g + rr;
        sC[rr*64 + pp]      = ld_cb(tch, tcl, row, h, pp);
        sC[rr*64 + pp + 32] = ld_cb(tch, tcl, row, h, pp + 32);
    }
    {
        int pbase = ((b * NCC + c) * HH + h) * 4096;
        for (int t = 0; t < 16; t++) {
            int idx = tid + t * 256;
            sP[idx] = g_prev[pbase + idx];
        }
    }
    __syncthreads();

    float accD[8][4], accO[8][4];
#pragma unroll
    for (int i = 0; i < 8; i++)
#pragma unroll
        for (int j = 0; j < 4; j++) { accD[i][j] = 0.f; accO[i][j] = 0.f; }
    for (int n = 0; n < 64; n++)
#pragma unroll
        for (int i = 0; i < 8; i++)
#pragma unroll
            for (int j = 0; j < 4; j++)
                accO[i][j] += sC[(ty*8+i)*64 + n] * sP[(tx*4+j)*64 + n];

    for (int stile = 0; stile < SL/64; stile++) {
        for (int t = 0; t < 8; t++) {
            int pr = tid + t * 256;
            int rr = pr >> 5, pp = pr & 31;
            int row = chunk_row + stile*64 + rr;
            sB[rr*64 + pp]      = ld_cb(tbh, tbl, row, h, pp);
            sB[rr*64 + pp + 32] = ld_cb(tbh, tbl, row, h, pp + 32);
            const float* xx = g_x + (size_t)row * DD + h * 64;
            sX[rr*64 + pp]      = xx[pp];
            sX[rr*64 + pp + 32] = xx[pp + 32];
        }
        __syncthreads();
        for (int t = 0; t < 32; t++) {
            int idx = tid + t * 256;
            int l = idx >> 6, sIn = idx & 63;
            int sg = stile*64 + sIn;
            float v = 0.f;
            if (sg <= l0g + l) {
                for (int n = 0; n < 64; n++)
                    v += sC[l*64 + n] * sB[sIn*64 + n];
                v *= expf(acs[l0g + l] - acs[sg]);
            }
            sS[idx] = v;
        }
        __syncthreads();
        for (int s = 0; s < 64; s++)
#pragma unroll
            for (int i = 0; i < 8; i++)
#pragma unroll
                for (int j = 0; j < 4; j++)
                    accD[i][j] += sS[(ty*8+i)*64 + s] * sX[s*64 + tx*4 + j];
        __syncthreads();
    }
#pragma unroll
    for (int i = 0; i < 8; i++) {
        int lr = ty*8 + i;
        int row = chunk_row + l0g + lr;
        float e = expf(acs[l0g + lr]);
        uint32_t tile = (uint32_t)(row >> 7) * 16u + (uint32_t)h;
#pragma unroll
        for (int j = 0; j < 4; j++) {
            float v = accD[i][j] + e * accO[i][j];
            float hh, llv;
            split2(v, hh, llv);
            int col = tx*4 + j;
            uint32_t off = ((uint32_t)tile << 14) +
                           swz((uint32_t)((row & 127)*128 + col*2));
            *(__nv_bfloat16*)(yhi + off) = __float2bfloat16(hh);
            *(__nv_bfloat16*)(ylo + off) = __float2bfloat16(llv);
        }
    }
#endif
}

// ---------------------------------------------------------------------------
// kernel_launch
// ---------------------------------------------------------------------------
extern "C" void kernel_launch(void* const* d_in, const int* in_sizes, int n_in,
                              void* d_out, int out_size) {
    (void)in_sizes; (void)n_in; (void)out_size;
    const float* hs   = (const float*)d_in[0];
    const float* cosp = (const float*)d_in[1];
    const float* sinp = (const float*)d_in[2];
    const float* Wc   = (const float*)d_in[3];
    const float* Wb   = (const float*)d_in[4];
    const float* Wdt  = (const float*)d_in[5];
    const float* Wx   = (const float*)d_in[6];
    const float* Wout = (const float*)d_in[7];
    const float* A    = (const float*)d_in[8];
    float* out = (float*)d_out;
    float* fs  = out + (size_t)MM * DD;

    float *px;
    char *ahi, *alo, *whi, *wlo, *tch, *tcl, *tbh, *tbl;
    cudaGetSymbolAddress((void**)&px, g_x);
    cudaGetSymbolAddress((void**)&ahi, g_ahi);
    cudaGetSymbolAddress((void**)&alo, g_alo);
    cudaGetSymbolAddress((void**)&whi, g_wt_hi);
    cudaGetSymbolAddress((void**)&wlo, g_wt_lo);
    cudaGetSymbolAddress((void**)&tch, g_tc_hi);
    cudaGetSymbolAddress((void**)&tcl, g_tc_lo);
    cudaGetSymbolAddress((void**)&tbh, g_tb_hi);
    cudaGetSymbolAddress((void**)&tbl, g_tb_lo);

    int gemm_smem = 1024 + 2 * BUF_STRIDE;
    int prep_smem = 16 * 1028 * 4;
    cudaFuncSetAttribute(gemm3, cudaFuncAttributeMaxDynamicSharedMemorySize, gemm_smem);
    cudaFuncSetAttribute(gemm_t, cudaFuncAttributeMaxDynamicSharedMemorySize, gemm_smem);
    cudaFuncSetAttribute(prep, cudaFuncAttributeMaxDynamicSharedMemorySize, prep_smem);
    cudaFuncSetAttribute(flash_k, cudaFuncAttributeMaxDynamicSharedMemorySize, FL_SMEM);

    prep<<<PREP_FS + PREP_WS + PREP_DT, 256, prep_smem>>>(
        hs, Wc, Wb, Wx, Wout, Wdt, ahi, alo, whi, wlo);

    dim3 g3(12, MM / 128);
    gemm3<<<g3, 256, gemm_smem>>>(ahi, alo, whi, wlo, cosp, sinp,
                                  tch, tcl, tbh, tbl, px);

    kb_kernel<<<BB * NCC * HH, 256>>>(tbh, tbl, A);
    kc_kernel<<<BB * HH * 16, 256>>>(fs);

    flash_k<<<BB * NCC * HH * 2, 256, FL_SMEM>>>(tch, tcl, tbh, tbl, ahi, alo);

    dim3 gg(GN / 256, MM / 128);
    gemm_t<<<gg, 256, gemm_smem>>>(ahi, alo, whi + 3*WSZB, wlo + 3*WSZB, out);
}

// round 17
// speedup vs baseline: 1.0909x; 1.0621x over previous
#include <cuda_runtime.h>
#include <cuda_bf16.h>
#include <math.h>
#include <stdint.h>

// Problem constants (fixed by the dataset)
#define BB  2
#define LL  8192
#define DD  1024
#define HH  16
#define PP  64
#define CLc 256
#define NCC 32
#define MM  (BB*LL)   // 16384 rows

#if defined(__CUDA_ARCH_FEAT_SM103_ALL) || defined(__CUDA_ARCH_FEAT_SM100_ALL) || \
    defined(__CUDA_ARCH_FEAT_SM101_ALL) || defined(__CUDA_ARCH_SPECIFIC__)
#define HAS_TCGEN05 1
#else
#define HAS_TCGEN05 0
#endif

#define WSZB ((size_t)2 * DD * DD)   // bytes per bf16 weight matrix

// ---------------------------------------------------------------------------
// Scratch
// ---------------------------------------------------------------------------
__device__ float g_x[BB*LL*DD];     // PRE-SCALED x*dt (fp32)
__device__ float g_dt[BB*LL*HH];
__device__ float g_ac[BB*LL*HH];
__device__ float g_cdec[BB*NCC*HH];
__device__ float g_states[BB*NCC*HH*PP*PP];
__device__ float g_prev[BB*NCC*HH*PP*PP];

// c and b as per-(rowblock,head) 16KB swizzled bf16 tiles:
//   tile = (row>>7)*HH + h ; byte off = tile*16384 + swz((row&127)*128 + p*2)
__device__ __align__(1024) __nv_bfloat16 g_tc_hi[MM*DD];
__device__ __align__(1024) __nv_bfloat16 g_tc_lo[MM*DD];
__device__ __align__(1024) __nv_bfloat16 g_tb_hi[MM*DD];
__device__ __align__(1024) __nv_bfloat16 g_tb_lo[MM*DD];

// TILED bf16 GEMM operands
__device__ __align__(1024) __nv_bfloat16 g_ahi[MM*DD];
__device__ __align__(1024) __nv_bfloat16 g_alo[MM*DD];
__device__ __align__(1024) __nv_bfloat16 g_wt_hi[4][DD*DD];
__device__ __align__(1024) __nv_bfloat16 g_wt_lo[4][DD*DD];

// ---------------------------------------------------------------------------
// Helpers
// ---------------------------------------------------------------------------
__device__ __forceinline__ uint32_t smem_u32(const void* p) {
    uint32_t a;
    asm("{ .reg .u64 t; cvta.to.shared.u64 t, %1; cvt.u32.u64 %0, t; }"
        : "=r"(a) : "l"(p));
    return a;
}
__device__ __forceinline__ uint32_t swz(uint32_t off) { return off ^ ((off >> 3) & 0x70); }

__device__ __forceinline__ void split2(float v, float& hi, float& lo) {
    __nv_bfloat16 h = __float2bfloat16(v);
    hi = __bfloat162float(h);
    lo = v - hi;
}
__device__ __forceinline__ void split_pack2(float v0, float v1,
                                            uint32_t& hi2, uint32_t& lo2) {
    asm("cvt.rn.bf16x2.f32 %0, %1, %2;" : "=r"(hi2) : "f"(v1), "f"(v0));
    float h0 = __uint_as_float(hi2 << 16);
    float h1 = __uint_as_float(hi2 & 0xFFFF0000u);
    asm("cvt.rn.bf16x2.f32 %0, %1, %2;" : "=r"(lo2) : "f"(v1 - h1), "f"(v0 - h0));
}
__device__ __forceinline__ float2 unsplit2(uint32_t hv, uint32_t lv) {
    float a = __uint_as_float(hv << 16) + __uint_as_float(lv << 16);
    float b = __uint_as_float(hv & 0xFFFF0000u) + __uint_as_float(lv & 0xFFFF0000u);
    return make_float2(a, b);
}
__device__ __forceinline__ size_t cb_off(int row, int h, int p) {
    size_t tile = (size_t)((row >> 7) * HH + h);
    return (tile << 14) + swz(((uint32_t)(row & 127) << 7) + ((uint32_t)p << 1));
}
__device__ __forceinline__ float ld_cb(const char* hi, const char* lo, int row, int h, int p) {
    size_t o = cb_off(row, h, p);
    return __bfloat162float(*(const __nv_bfloat16*)(hi + o)) +
           __bfloat162float(*(const __nv_bfloat16*)(lo + o));
}
__device__ __forceinline__ uint32_t a_tile_off(int row, int k) {
    uint32_t tile = (uint32_t)(row >> 7) * 16u + (uint32_t)(k >> 6);
    return (tile << 14) + swz(((uint32_t)(row & 127) << 7) + ((uint32_t)(k & 63) << 1));
}
__device__ __forceinline__ uint32_t b_tile_off(int n, int k) {
    uint32_t tile = (uint32_t)(n >> 8) * 16u + (uint32_t)(k >> 6);
    return (tile << 15) + swz(((uint32_t)(n & 255) << 7) + ((uint32_t)(k & 63) << 1));
}

#if HAS_TCGEN05
__device__ __forceinline__ uint32_t elect_one() {
    uint32_t pred;
    asm volatile("{\n\t.reg .pred p;\n\telect.sync _|p, 0xFFFFFFFF;\n\t"
                 "selp.b32 %0, 1, 0, p;\n\t}" : "=r"(pred));
    return pred;
}
#define MBAR_INIT(a, c) \
    asm volatile("mbarrier.init.shared.b64 [%0], %1;" :: "r"(a), "r"(c) : "memory")
#define MBAR_EXPECT_TX(a, n) \
    asm volatile("mbarrier.arrive.expect_tx.shared.b64 _, [%0], %1;" :: "r"(a), "r"(n) : "memory")
#define MBAR_WAIT(a, ph) do { \
    asm volatile("{\n\t.reg .pred P1;\n\t" \
        "WL_%=:\n\t" \
        "mbarrier.try_wait.parity.acquire.cta.shared::cta.b64 P1, [%0], %1, 0x989680;\n\t" \
        "@P1 bra.uni WD_%=;\n\tbra.uni WL_%=;\n\tWD_%=:\n\t}" \
        :: "r"(a), "r"(ph) : "memory"); \
} while (0)
#define BULK_G2S(dst, src, n, mbar) \
    asm volatile("cp.async.bulk.shared::cta.global.mbarrier::complete_tx::bytes " \
                 "[%0], [%1], %2, [%3];" \
                 :: "r"(dst), "l"(src), "r"(n), "r"(mbar) : "memory")
#define TC_ALLOC(sa, n) \
    asm volatile("tcgen05.alloc.cta_group::1.sync.aligned.shared::cta.b32 [%0], %1;" \
                 :: "r"(sa), "r"(n) : "memory")
#define TC_DEALLOC(t, n) \
    asm volatile("tcgen05.dealloc.cta_group::1.sync.aligned.b32 %0, %1;" :: "r"(t), "r"(n))
#define TC_COMMIT(a) \
    asm volatile("tcgen05.commit.cta_group::1.mbarrier::arrive::one.shared::cluster.b64 [%0];" \
                 :: "r"(a) : "memory")
#define TC_FENCE_AFTER() asm volatile("tcgen05.fence::after_thread_sync;" ::: "memory")
#define TC_FENCE_BEFORE() asm volatile("tcgen05.fence::before_thread_sync;" ::: "memory")
#define TC_WAIT_LD() asm volatile("tcgen05.wait::ld.sync.aligned;" ::: "memory")
#define FENCE_ASYNC() asm volatile("fence.proxy.async.shared::cta;" ::: "memory")

__device__ __forceinline__ void mma_f16_ss(uint32_t d, uint64_t ad, uint64_t bd,
                                           uint32_t idesc, uint32_t en) {
    asm volatile("{\n\t.reg .pred p;\n\tsetp.ne.u32 p, %4, 0;\n\t"
                 "tcgen05.mma.cta_group::1.kind::f16 [%0], %1, %2, %3, {%5,%5,%5,%5}, p;\n\t}"
                 :: "r"(d), "l"(ad), "l"(bd), "r"(idesc), "r"(en), "r"(0u) : "memory");
}
__device__ __forceinline__ void ldtm32(uint32_t* r, uint32_t ta) {
    asm volatile("tcgen05.ld.sync.aligned.32x32b.x32.b32 "
        "{%0,%1,%2,%3,%4,%5,%6,%7,%8,%9,%10,%11,%12,%13,%14,%15,"
        "%16,%17,%18,%19,%20,%21,%22,%23,%24,%25,%26,%27,%28,%29,%30,%31}, [%32];"
        : "=r"(r[0]),"=r"(r[1]),"=r"(r[2]),"=r"(r[3]),"=r"(r[4]),"=r"(r[5]),"=r"(r[6]),"=r"(r[7]),
          "=r"(r[8]),"=r"(r[9]),"=r"(r[10]),"=r"(r[11]),"=r"(r[12]),"=r"(r[13]),"=r"(r[14]),"=r"(r[15]),
          "=r"(r[16]),"=r"(r[17]),"=r"(r[18]),"=r"(r[19]),"=r"(r[20]),"=r"(r[21]),"=r"(r[22]),"=r"(r[23]),
          "=r"(r[24]),"=r"(r[25]),"=r"(r[26]),"=r"(r[27]),"=r"(r[28]),"=r"(r[29]),"=r"(r[30]),"=r"(r[31])
        : "r"(ta));
}
static constexpr uint64_t DESC_BASE =
    (uint64_t(2) << 61) | (uint64_t(1) << 46) | (uint64_t(64) << 32) | (uint64_t(1) << 16);
__device__ __forceinline__ uint64_t mk_desc(uint32_t addr) {
    return DESC_BASE | ((uint64_t)(addr >> 4) & 0x3FFF);
}
#define IDESC_N(N) ((1u<<4)|(1u<<7)|(1u<<10)|(((N)/8u)<<17)|(8u<<24))
#endif  // HAS_TCGEN05

// ---------------------------------------------------------------------------
// prep: fsplit (blocks [0,8192)) + wsplit x4 ([8192,12288)) + dt2 ([12288,12800))
// ---------------------------------------------------------------------------
#define PREP_FS 8192
#define PREP_WS 4096
#define PREP_DT 512

__global__ __launch_bounds__(256) void prep(
        const float* __restrict__ hs,
        const float* __restrict__ Wc, const float* __restrict__ Wb,
        const float* __restrict__ Wx, const float* __restrict__ Wout,
        const float* __restrict__ Wdt,
        char* __restrict__ ahi, char* __restrict__ alo,
        char* __restrict__ whi, char* __restrict__ wlo) {
    extern __shared__ float sw[];
    int bid = blockIdx.x, tid = threadIdx.x;

    if (bid < PREP_FS) {
        int t = bid * 256 + tid;
        int row = t >> 7;
        int k8 = t & 127;
        const float4* p = (const float4*)(hs + ((size_t)row << 10) + (k8 << 3));
        float4 v0 = p[0], v1 = p[1];
        uint4 hv, lv;
        split_pack2(v0.x, v0.y, hv.x, lv.x);
        split_pack2(v0.z, v0.w, hv.y, lv.y);
        split_pack2(v1.x, v1.y, hv.z, lv.z);
        split_pack2(v1.z, v1.w, hv.w, lv.w);
        uint32_t tile = (uint32_t)(row >> 7) * 16u + (uint32_t)(k8 >> 3);
        uint32_t off = (tile << 14) + swz(((uint32_t)(row & 127) << 7) + ((uint32_t)(k8 & 7) << 4));
        *(uint4*)(ahi + off) = hv;
        *(uint4*)(alo + off) = lv;
    } else if (bid < PREP_FS + PREP_WS) {
        int q = bid - PREP_FS;
        int m = q >> 10;
        const float* W = (m == 0) ? Wc : (m == 1) ? Wb : (m == 2) ? Wx : Wout;
        char* Thi = whi + (size_t)m * WSZB;
        char* Tlo = wlo + (size_t)m * WSZB;
        int qq = q & 1023;
        int bx = (qq & 31) * 32, by = (qq >> 5) * 32;
        float (*t)[33] = (float(*)[33])sw;
        int x = tid & 31, y = tid >> 5;
#pragma unroll
        for (int j = 0; j < 4; j++)
            t[y + j*8][x] = W[(size_t)(by + y + j*8) * DD + bx + x];
        __syncthreads();
#pragma unroll
        for (int j = 0; j < 4; j++) {
            float v = t[x][y + j*8];
            float h, l;
            split2(v, h, l);
            int n = bx + y + j*8, k = by + x;
            uint32_t off = b_tile_off(n, k);
            *(__nv_bfloat16*)(Thi + off) = __float2bfloat16(h);
            *(__nv_bfloat16*)(Tlo + off) = __float2bfloat16(l);
        }
    } else {
        int blk = bid - PREP_FS - PREP_WS;
        for (int i = tid; i < 16384; i += 256)
            sw[(i & 15) * 1028 + (i >> 4)] = Wdt[i];
        __syncthreads();
        int w = tid >> 5, l = tid & 31;
        int row0 = blk * 32 + w * 4;
        float acc[4][16];
#pragma unroll
        for (int r = 0; r < 4; r++)
#pragma unroll
            for (int n = 0; n < 16; n++) acc[r][n] = 0.f;
#pragma unroll
        for (int it = 0; it < 8; it++) {
            int k0 = it * 128 + l * 4;
            float4 h[4];
#pragma unroll
            for (int r = 0; r < 4; r++)
                h[r] = *(const float4*)&hs[(size_t)(row0 + r) * DD + k0];
#pragma unroll
            for (int n = 0; n < 16; n++) {
                float4 wv = *(const float4*)&sw[n * 1028 + k0];
#pragma unroll
                for (int r = 0; r < 4; r++)
                    acc[r][n] += h[r].x*wv.x + h[r].y*wv.y + h[r].z*wv.z + h[r].w*wv.w;
            }
        }
#pragma unroll
        for (int off = 16; off; off >>= 1)
#pragma unroll
            for (int r = 0; r < 4; r++)
#pragma unroll
                for (int n = 0; n < 16; n++)
                    acc[r][n] += __shfl_xor_sync(0xFFFFFFFFu, acc[r][n], off);
        if (l == 0) {
#pragma unroll
            for (int r = 0; r < 4; r++)
#pragma unroll
                for (int n = 0; n < 16; n++) {
                    float s = acc[r][n];
                    g_dt[(row0 + r) * HH + n] = fmaxf(s, 0.f) + log1pf(expf(-fabsf(s)));
                }
        }
    }
}

// ---------------------------------------------------------------------------
// GEMM common constants
// ---------------------------------------------------------------------------
#define GK 1024
#define GN 1024
#define NCHUNK 16
#define BUF_STRIDE 98304
#define GIDESC ((1u<<4)|(1u<<7)|(1u<<10)|((256u/8)<<17)|((128u/16)<<24))

// ---------------------------------------------------------------------------
// gemm3: merged projection GEMM. grid=(12,128). mode=bn>>2: 0=c 1=b 2=x.
// ---------------------------------------------------------------------------
__global__ __launch_bounds__(256, 1) void gemm3(
        const char* __restrict__ Ahi, const char* __restrict__ Alo,
        const char* __restrict__ Whi, const char* __restrict__ Wlo,
        const float* __restrict__ cosp, const float* __restrict__ sinp,
        char* __restrict__ tch, char* __restrict__ tcl,
        char* __restrict__ tbh, char* __restrict__ tbl,
        float* __restrict__ px) {
    extern __shared__ char sm[];
    int tid = threadIdx.x;
    int wid = tid >> 5, lid = tid & 31;
    int bn = blockIdx.x, bm = blockIdx.y;
    int mode = bn >> 2;
#if HAS_TCGEN05
    uint32_t sbase = smem_u32(sm);
    if (tid == 0) {
        MBAR_INIT(sbase + 8, 1);  MBAR_INIT(sbase + 16, 1);
        MBAR_INIT(sbase + 24, 1); MBAR_INIT(sbase + 32, 1);
    }
    if (wid == 0) TC_ALLOC(sbase, 256);
    __syncthreads();
    uint32_t tmem;
    asm volatile("ld.shared.b32 %0, [%1];" : "=r"(tmem) : "r"(sbase));

    if (wid == 0 && elect_one()) {
        auto load = [&](int chunk, int b) {
            uint32_t mb = sbase + 8 + (uint32_t)b * 8;
            MBAR_EXPECT_TX(mb, 98304u);
            uint32_t d = sbase + 1024u + (uint32_t)b * BUF_STRIDE;
            size_t ao = ((size_t)bm * 16 + chunk) << 14;
            size_t bo = ((size_t)bn * 16 + chunk) << 15;
            BULK_G2S(d,          Ahi + ao, 16384u, mb);
            BULK_G2S(d + 16384,  Alo + ao, 16384u, mb);
            BULK_G2S(d + 32768,  Whi + bo, 32768u, mb);
            BULK_G2S(d + 65536,  Wlo + bo, 32768u, mb);
        };
        load(0, 0);
        load(1, 1);
        int f0 = 0, f1 = 0, e0 = 0, e1 = 0;
        for (int k = 0; k < NCHUNK; k++) {
            int b = k & 1;
            if (b == 0) { MBAR_WAIT(sbase + 8, f0);  f0 ^= 1; }
            else        { MBAR_WAIT(sbase + 16, f1); f1 ^= 1; }
            uint32_t boff = sbase + 1024u + (uint32_t)b * BUF_STRIDE;
            uint64_t dah = mk_desc(boff);
            uint64_t dal = mk_desc(boff + 16384);
            uint64_t dbh = mk_desc(boff + 32768);
            uint64_t dbl = mk_desc(boff + 65536);
#pragma unroll
            for (int ks = 0; ks < 4; ks++) {
                mma_f16_ss(tmem, dah + ks*2, dbh + ks*2, GIDESC,
                           (k == 0 && ks == 0) ? 0u : 1u);
                mma_f16_ss(tmem, dah + ks*2, dbl + ks*2, GIDESC, 1u);
                mma_f16_ss(tmem, dal + ks*2, dbh + ks*2, GIDESC, 1u);
            }
            TC_COMMIT(sbase + 24 + (uint32_t)b * 8);
            if (k + 2 < NCHUNK) {
                if (b == 0) { MBAR_WAIT(sbase + 24, e0); e0 ^= 1; }
                else        { MBAR_WAIT(sbase + 32, e1); e1 ^= 1; }
                load(k + 2, b);
            }
        }
        MBAR_WAIT(sbase + 24, e0);
        MBAR_WAIT(sbase + 32, e1);
    }
    __syncthreads();
    TC_FENCE_AFTER();

    {
        int sub = wid & 3, grp = wid >> 2;
        int row = bm * 128 + sub * 32 + lid;
        if (mode < 2) {
            char* Thi = (mode == 0) ? tch : tbh;
            char* Tlo = (mode == 0) ? tcl : tbl;
            const float* cr = cosp + (size_t)row * 64;
            const float* sr = sinp + (size_t)row * 64;
            uint32_t rb = (uint32_t)(row & 127) * 128;
#pragma unroll
            for (int cb2 = 0; cb2 < 2; cb2++) {
                int head64 = (grp * 2 + cb2) * 64;
                uint32_t r0[32], r1[32];
                ldtm32(r0, tmem + head64);      TC_WAIT_LD();
                ldtm32(r1, tmem + head64 + 32); TC_WAIT_LD();
                int hidx = (bn & 3) * 4 + grp * 2 + cb2;
                size_t tb = ((size_t)((row >> 7) * HH + hidx)) << 14;
#pragma unroll
                for (int j = 0; j < 32; j += 4) {
                    float4 c1 = *(const float4*)(cr + j);
                    float4 s1 = *(const float4*)(sr + j);
                    float4 c2 = *(const float4*)(cr + j + 32);
                    float4 s2 = *(const float4*)(sr + j + 32);
                    float a0 = __uint_as_float(r0[j]),   a1 = __uint_as_float(r0[j+1]);
                    float a2 = __uint_as_float(r0[j+2]), a3 = __uint_as_float(r0[j+3]);
                    float q0 = __uint_as_float(r1[j]),   q1 = __uint_as_float(r1[j+1]);
                    float q2 = __uint_as_float(r1[j+2]), q3 = __uint_as_float(r1[j+3]);
                    uint2 h1, l1, h2, l2;
                    split_pack2(a0*c1.x - q0*s1.x, a1*c1.y - q1*s1.y, h1.x, l1.x);
                    split_pack2(a2*c1.z - q2*s1.z, a3*c1.w - q3*s1.w, h1.y, l1.y);
                    split_pack2(q0*c2.x + a0*s2.x, q1*c2.y + a1*s2.y, h2.x, l2.x);
                    split_pack2(q2*c2.z + a2*s2.z, q3*c2.w + a3*s2.w, h2.y, l2.y);
                    uint32_t o1 = swz(rb + j * 2);
                    uint32_t o2 = swz(rb + 64 + j * 2);
                    *(uint2*)(Thi + tb + o1) = h1;
                    *(uint2*)(Tlo + tb + o1) = l1;
                    *(uint2*)(Thi + tb + o2) = h2;
                    *(uint2*)(Tlo + tb + o2) = l2;
                }
            }
        } else {
            int bnc = (bn & 3) * 256;
            float* crow = px + (size_t)row * GN + bnc;
#pragma unroll
            for (int cb2 = 0; cb2 < 2; cb2++) {
                int head64 = (grp * 2 + cb2) * 64;
                uint32_t r0[32], r1[32];
                ldtm32(r0, tmem + head64);      TC_WAIT_LD();
                ldtm32(r1, tmem + head64 + 32); TC_WAIT_LD();
                int hidx = (bnc >> 6) + grp * 2 + cb2;
                float dtv = g_dt[row * HH + hidx];
#pragma unroll
                for (int j = 0; j < 32; j += 4) {
                    float4 o1 = make_float4(__uint_as_float(r0[j])   * dtv,
                                            __uint_as_float(r0[j+1]) * dtv,
                                            __uint_as_float(r0[j+2]) * dtv,
                                            __uint_as_float(r0[j+3]) * dtv);
                    float4 o2 = make_float4(__uint_as_float(r1[j])   * dtv,
                                            __uint_as_float(r1[j+1]) * dtv,
                                            __uint_as_float(r1[j+2]) * dtv,
                                            __uint_as_float(r1[j+3]) * dtv);
                    *(float4*)(crow + head64 + j)      = o1;
                    *(float4*)(crow + head64 + 32 + j) = o2;
                }
            }
        }
        TC_FENCE_BEFORE();
    }
    __syncthreads();
    if (wid == 0) TC_DEALLOC(tmem, 256);
#else
    // CUDA-core fallback
    int tx = tid & 15, ty = tid >> 4;
    int bmr = bm * 128;
    float* sA = (float*)sm;
    float* sB = (float*)(sm + 8192);
    float* stg = (float*)(sm + 16384);
    auto rdA = [&](const char* p, int row, int k) {
        return __bfloat162float(*(const __nv_bfloat16*)(p + a_tile_off(row, k)));
    };
    auto rdBW = [&](const char* p, int gn, int k) {
        uint32_t tile = (uint32_t)(gn >> 8) * 16u + (uint32_t)(k >> 6);
        uint32_t off = (tile << 15) + swz(((uint32_t)(gn & 255) << 7) + ((uint32_t)(k & 63) << 1));
        return __bfloat162float(*(const __nv_bfloat16*)(p + off));
    };
    for (int half = 0; half < 2; half++) {
        int bn2 = bn * 256 + half * 128;
        float acc[8][8];
#pragma unroll
        for (int i = 0; i < 8; i++)
#pragma unroll
            for (int j = 0; j < 8; j++) acc[i][j] = 0.f;
        for (int k0 = 0; k0 < GK; k0 += 16) {
            for (int i = tid; i < 2048; i += 256) {
                int r = i >> 4, kk = i & 15;
                sA[kk*128 + r] = rdA(Ahi, bmr + r, k0 + kk) + rdA(Alo, bmr + r, k0 + kk);
                sB[kk*128 + r] = rdBW(Whi, bn2 + r, k0 + kk) + rdBW(Wlo, bn2 + r, k0 + kk);
            }
            __syncthreads();
#pragma unroll
            for (int kk = 0; kk < 16; kk++) {
                float a[8], b[8];
#pragma unroll
                for (int i = 0; i < 4; i++) {
                    a[i] = sA[kk*128 + ty*4 + i];
                    a[i+4] = sA[kk*128 + 64 + ty*4 + i];
                    b[i] = sB[kk*128 + tx*4 + i];
                    b[i+4] = sB[kk*128 + 64 + tx*4 + i];
                }
#pragma unroll
                for (int i = 0; i < 8; i++)
#pragma unroll
                    for (int j = 0; j < 8; j++) acc[i][j] += a[i] * b[j];
            }
            __syncthreads();
        }
#pragma unroll
        for (int i = 0; i < 8; i++) {
            int rl = (i < 4) ? (ty*4 + i) : (64 + ty*4 + i - 4);
#pragma unroll
            for (int j = 0; j < 8; j++) {
                int cl = (j < 4) ? (tx*4 + j) : (64 + tx*4 + j - 4);
                stg[rl * 128 + cl] = acc[i][j];
            }
        }
        __syncthreads();
        if (mode < 2) {
            char* Thi = (mode == 0) ? tch : tbh;
            char* Tlo = (mode == 0) ? tcl : tbl;
            for (int u = tid; u < 128 * 64; u += 256) {
                int rr = u >> 6, ps = u & 63;
                int head = ps >> 5, p = ps & 31;
                int row = bmr + rr;
                float a = stg[rr*128 + head*64 + p];
                float q = stg[rr*128 + head*64 + p + 32];
                float c1 = cosp[row*64 + p],      s1 = sinp[row*64 + p];
                float c2 = cosp[row*64 + p + 32], s2 = sinp[row*64 + p + 32];
                float v1 = a * c1 - q * s1;
                float v2 = q * c2 + a * s2;
                int hidx = (bn & 3) * 4 + half * 2 + head;
                float hh, llv;
                split2(v1, hh, llv);
                size_t o = cb_off(row, hidx, p);
                *(__nv_bfloat16*)(Thi + o) = __float2bfloat16(hh);
                *(__nv_bfloat16*)(Tlo + o) = __float2bfloat16(llv);
                split2(v2, hh, llv);
                o = cb_off(row, hidx, p + 32);
                *(__nv_bfloat16*)(Thi + o) = __float2bfloat16(hh);
                *(__nv_bfloat16*)(Tlo + o) = __float2bfloat16(llv);
            }
        } else {
            int bnc = (bn & 3) * 256 + half * 128;
            for (int u = tid; u < 128 * 128; u += 256) {
                int rr = u >> 7, cl = u & 127;
                int row = bmr + rr;
                int hidx = (bnc + cl) >> 6;
                px[(size_t)row * GN + bnc + cl] = stg[rr*128 + cl] * g_dt[row * HH + hidx];
            }
        }
        __syncthreads();
    }
#endif
}

// ---------------------------------------------------------------------------
// gemm_t: plain GEMM (final Wout). grid=(4,128).
// ---------------------------------------------------------------------------
__global__ __launch_bounds__(256, 1) void gemm_t(
        const char* __restrict__ Ahi, const char* __restrict__ Alo,
        const char* __restrict__ Bhi, const char* __restrict__ Blo,
        float* __restrict__ C) {
    extern __shared__ char sm[];
#if HAS_TCGEN05
    uint32_t sbase = smem_u32(sm);
    int tid = threadIdx.x;
    int wid = tid >> 5, lid = tid & 31;
    int bn = blockIdx.x, bm = blockIdx.y;

    if (tid == 0) {
        MBAR_INIT(sbase + 8, 1);  MBAR_INIT(sbase + 16, 1);
        MBAR_INIT(sbase + 24, 1); MBAR_INIT(sbase + 32, 1);
    }
    if (wid == 0) TC_ALLOC(sbase, 256);
    __syncthreads();
    uint32_t tmem;
    asm volatile("ld.shared.b32 %0, [%1];" : "=r"(tmem) : "r"(sbase));

    if (wid == 0 && elect_one()) {
        auto load = [&](int chunk, int b) {
            uint32_t mb = sbase + 8 + (uint32_t)b * 8;
            MBAR_EXPECT_TX(mb, 98304u);
            uint32_t d = sbase + 1024u + (uint32_t)b * BUF_STRIDE;
            size_t ao = ((size_t)bm * 16 + chunk) << 14;
            size_t bo = ((size_t)bn * 16 + chunk) << 15;
            BULK_G2S(d,          Ahi + ao, 16384u, mb);
            BULK_G2S(d + 16384,  Alo + ao, 16384u, mb);
            BULK_G2S(d + 32768,  Bhi + bo, 32768u, mb);
            BULK_G2S(d + 65536,  Blo + bo, 32768u, mb);
        };
        load(0, 0);
        load(1, 1);
        int f0 = 0, f1 = 0, e0 = 0, e1 = 0;
        for (int k = 0; k < NCHUNK; k++) {
            int b = k & 1;
            if (b == 0) { MBAR_WAIT(sbase + 8, f0);  f0 ^= 1; }
            else        { MBAR_WAIT(sbase + 16, f1); f1 ^= 1; }
            uint32_t boff = sbase + 1024u + (uint32_t)b * BUF_STRIDE;
            uint64_t dah = mk_desc(boff);
            uint64_t dal = mk_desc(boff + 16384);
            uint64_t dbh = mk_desc(boff + 32768);
            uint64_t dbl = mk_desc(boff + 65536);
#pragma unroll
            for (int ks = 0; ks < 4; ks++) {
                mma_f16_ss(tmem, dah + ks*2, dbh + ks*2, GIDESC,
                           (k == 0 && ks == 0) ? 0u : 1u);
                mma_f16_ss(tmem, dah + ks*2, dbl + ks*2, GIDESC, 1u);
                mma_f16_ss(tmem, dal + ks*2, dbh + ks*2, GIDESC, 1u);
            }
            TC_COMMIT(sbase + 24 + (uint32_t)b * 8);
            if (k + 2 < NCHUNK) {
                if (b == 0) { MBAR_WAIT(sbase + 24, e0); e0 ^= 1; }
                else        { MBAR_WAIT(sbase + 32, e1); e1 ^= 1; }
                load(k + 2, b);
            }
        }
        MBAR_WAIT(sbase + 24, e0);
        MBAR_WAIT(sbase + 32, e1);
    }
    __syncthreads();
    TC_FENCE_AFTER();

    {
        int sub = wid & 3, grp = wid >> 2;
        int row = bm * 128 + sub * 32 + lid;
        float* crow = C + (size_t)row * GN + bn * 256;
#pragma unroll
        for (int cb = grp * 4; cb < grp * 4 + 4; cb++) {
            uint32_t r[32];
            ldtm32(r, tmem + cb * 32);
            TC_WAIT_LD();
#pragma unroll
            for (int j = 0; j < 8; j++) {
                float4 v = make_float4(__uint_as_float(r[j*4]), __uint_as_float(r[j*4+1]),
                                       __uint_as_float(r[j*4+2]), __uint_as_float(r[j*4+3]));
                *(float4*)(crow + cb * 32 + j * 4) = v;
            }
        }
        TC_FENCE_BEFORE();
    }
    __syncthreads();
    if (wid == 0) TC_DEALLOC(tmem, 256);
#else
    int tid = threadIdx.x;
    int tx = tid & 15, ty = tid >> 4;
    int bn = blockIdx.x * 256, bm = blockIdx.y * 128;
    float* sA = (float*)sm;
    float* sB = (float*)(sm + 8192);
    auto rdA = [&](const char* p, int row, int k) {
        return __bfloat162float(*(const __nv_bfloat16*)(p + a_tile_off(row, k)));
    };
    auto rdB = [&](const char* p, int n, int k) {
        return __bfloat162float(*(const __nv_bfloat16*)(p + b_tile_off(n, k)));
    };
    for (int half = 0; half < 2; half++) {
        int bn2 = bn + half * 128;
        float acc[8][8];
#pragma unroll
        for (int i = 0; i < 8; i++)
#pragma unroll
            for (int j = 0; j < 8; j++) acc[i][j] = 0.f;
        for (int k0 = 0; k0 < GK; k0 += 16) {
            for (int i = tid; i < 2048; i += 256) {
                int r = i >> 4, kk = i & 15;
                sA[kk*128 + r] = rdA(Ahi, bm + r, k0 + kk) + rdA(Alo, bm + r, k0 + kk);
                sB[kk*128 + r] = rdB(Bhi, bn2 + r, k0 + kk) + rdB(Blo, bn2 + r, k0 + kk);
            }
            __syncthreads();
#pragma unroll
            for (int kk = 0; kk < 16; kk++) {
                float a[8], b[8];
#pragma unroll
                for (int i = 0; i < 4; i++) {
                    a[i] = sA[kk*128 + ty*4 + i];
                    a[i+4] = sA[kk*128 + 64 + ty*4 + i];
                    b[i] = sB[kk*128 + tx*4 + i];
                    b[i+4] = sB[kk*128 + 64 + tx*4 + i];
                }
#pragma unroll
                for (int i = 0; i < 8; i++)
#pragma unroll
                    for (int j = 0; j < 8; j++) acc[i][j] += a[i] * b[j];
            }
            __syncthreads();
        }
#pragma unroll
        for (int i = 0; i < 8; i++) {
            int row = bm + ((i < 4) ? (ty*4 + i) : (64 + ty*4 + i - 4));
#pragma unroll
            for (int j = 0; j < 8; j++) {
                int col = bn2 + ((j < 4) ? (tx*4 + j) : (64 + tx*4 + j - 4));
                C[(size_t)row * GN + col] = acc[i][j];
            }
        }
        __syncthreads();
    }
#endif
}

// ---------------------------------------------------------------------------
// kb: fused acum (per-chunk cumsum of dt*A) + chunk states.
// ---------------------------------------------------------------------------
__global__ __launch_bounds__(256) void kb_kernel(const char* __restrict__ tbh,
                                                 const char* __restrict__ tbl,
                                                 const float* __restrict__ A) {
    __shared__ float sX[4096];
    __shared__ float sB[4096];
    __shared__ float sac[256];
    int bid = blockIdx.x;
    int h = bid & 15, c = (bid >> 4) & 31, b = bid >> 9;
    int tid = threadIdx.x, tx = tid & 15, ty = tid >> 4;
    int chunk_row = b * LL + c * CLc;

    sac[tid] = g_dt[(chunk_row + tid) * HH + h] * A[h];
    __syncthreads();
    for (int off = 1; off < 256; off <<= 1) {
        float u = (tid >= off) ? sac[tid - off] : 0.f;
        __syncthreads();
        sac[tid] += u;
        __syncthreads();
    }
    g_ac[(chunk_row + tid) * HH + h] = sac[tid];
    if (tid == 255) g_cdec[bid] = expf(sac[255]);
    __syncthreads();
    float aclast = sac[255];

    float acc[4][4];
#pragma unroll
    for (int i = 0; i < 4; i++)
#pragma unroll
        for (int j = 0; j < 4; j++) acc[i][j] = 0.f;

    for (int ltile = 0; ltile < 4; ltile++) {
        int r0 = chunk_row + ltile * 64;
#pragma unroll
        for (int t = 0; t < 2; t++) {
            int u = tid + t * 256;
            int rr = u >> 3, p8 = (u & 7) * 8;
            int row = r0 + rr;
            size_t to = (((size_t)((row >> 7) * HH + h)) << 14) +
                        swz(((uint32_t)(row & 127) << 7) + ((uint32_t)p8 << 1));
            uint4 hv = *(const uint4*)(tbh + to);
            uint4 lv = *(const uint4*)(tbl + to);
            float w = __expf(aclast - sac[ltile * 64 + rr]);
            float2 f0 = unsplit2(hv.x, lv.x);
            float2 f1 = unsplit2(hv.y, lv.y);
            float2 f2 = unsplit2(hv.z, lv.z);
            float2 f3 = unsplit2(hv.w, lv.w);
            *(float4*)&sB[rr*64 + p8]     = make_float4(f0.x*w, f0.y*w, f1.x*w, f1.y*w);
            *(float4*)&sB[rr*64 + p8 + 4] = make_float4(f2.x*w, f2.y*w, f3.x*w, f3.y*w);
            const float* xx = g_x + (size_t)row * DD + h * 64 + p8;
            *(float4*)&sX[rr*64 + p8]     = *(const float4*)xx;
            *(float4*)&sX[rr*64 + p8 + 4] = *(const float4*)(xx + 4);
        }
        __syncthreads();
#pragma unroll 4
        for (int l = 0; l < 64; l++) {
            float xv[4], bv[4];
#pragma unroll
            for (int i = 0; i < 4; i++) xv[i] = sX[l * 64 + ty * 4 + i];
#pragma unroll
            for (int j = 0; j < 4; j++) bv[j] = sB[l * 64 + tx * 4 + j];
#pragma unroll
            for (int i = 0; i < 4; i++)
#pragma unroll
                for (int j = 0; j < 4; j++) acc[i][j] += xv[i] * bv[j];
        }
        __syncthreads();
    }
    int sb = ((b * NCC + c) * HH + h) * 4096;
#pragma unroll
    for (int i = 0; i < 4; i++) {
        float4 v = make_float4(acc[i][0], acc[i][1], acc[i][2], acc[i][3]);
        *(float4*)&g_states[sb + (ty * 4 + i) * 64 + tx * 4] = v;
    }
}

// ---------------------------------------------------------------------------
// kc: sequential chunk scan, one element per thread. grid = BB*HH*16.
// ---------------------------------------------------------------------------
__global__ __launch_bounds__(256) void kc_kernel(float* __restrict__ fs) {
    int bid = blockIdx.x;
    int ks = bid & 15;
    int h = (bid >> 4) & 15;
    int b = bid >> 8;
    int e = ks * 256 + threadIdx.x;
    int bh = b * NCC * HH + h;
    float st = 0.f;
#pragma unroll 4
    for (int c = 0; c < NCC; c++) {
        float dec = g_cdec[(b * NCC + c) * HH + h];
        int base = (bh + c * HH) * 4096 + e;
        g_prev[base] = st;
        st = st * dec + g_states[base];
    }
    fs[(b * HH + h) * 4096 + e] = st;
}

// ---------------------------------------------------------------------------
// Flash kernel (512 threads / 16 warps): C/B via cp.async.bulk; X/P fills.
// ---------------------------------------------------------------------------
#define FL_SMEM 183296
#define FO_AC   64
#define FO_EC   1088
#define FO_CHI  3072
#define FO_CLO  19456
#define FO_BHI  35840
#define FO_BLO  68608
#define FO_XHI  101376
#define FO_XLO  134144
#define FO_PHI  166912
#define FO_PLO  175104

__global__ __launch_bounds__(512, 1) void flash_k(const char* __restrict__ tch,
                                                  const char* __restrict__ tcl,
                                                  const char* __restrict__ tbh,
                                                  const char* __restrict__ tbl,
                                                  char* __restrict__ yhi,
                                                  char* __restrict__ ylo) {
    extern __shared__ char sm[];
    int tid = threadIdx.x, wid = tid >> 5, lid = tid & 31;
    int bid = blockIdx.x;
    int half = bid & 1, h = (bid >> 1) & 15, c = (bid >> 5) & 31, b = bid >> 10;
    int chunk_row = b * LL + c * CLc;
    int l0g = half * 128;
    int SL = half ? 256 : 128;
    float* acs = (float*)(sm + FO_AC);
    float* ecol = (float*)(sm + FO_EC);

#if HAS_TCGEN05
    uint32_t sbase = smem_u32(sm);
    int nsl = SL / 128;
    if (tid == 0) {
        MBAR_INIT(sbase + 8, 1);  MBAR_INIT(sbase + 16, 1);
        MBAR_INIT(sbase + 24, 1); MBAR_INIT(sbase + 32, 1);
        MBAR_INIT(sbase + 40, 1);
    }
    if (wid == 0) TC_ALLOC(sbase, 512);
    __syncthreads();
    uint32_t tmem;
    asm volatile("ld.shared.b32 %0, [%1];" : "=r"(tmem) : "r"(sbase));

    if (tid == 0) {
        uint32_t nbytes = 32768u * (uint32_t)(1 + nsl);
        MBAR_EXPECT_TX(sbase + 40, nbytes);
        size_t ct = ((size_t)(((chunk_row + l0g) >> 7) * HH + h)) << 14;
        BULK_G2S(sbase + FO_CHI, tch + ct, 16384u, sbase + 40);
        BULK_G2S(sbase + FO_CLO, tcl + ct, 16384u, sbase + 40);
        for (int i = 0; i < nsl; i++) {
            size_t bt = ((size_t)(((chunk_row >> 7) + i) * HH + h)) << 14;
            BULK_G2S(sbase + FO_BHI + (uint32_t)i * 16384u, tbh + bt, 16384u, sbase + 40);
            BULK_G2S(sbase + FO_BLO + (uint32_t)i * 16384u, tbl + bt, 16384u, sbase + 40);
        }
    }

    if (tid < 256) acs[tid] = g_ac[(chunk_row + tid) * HH + h];
    __syncthreads();
    if (tid < 256) ecol[tid] = __expf(acs[tid & ~31] - acs[tid]);

    // X^T tile fill (512-thread strides)
    for (int t = 0; t < SL/32; t++) {
        int u = tid + t * 512;
        int p = u & 63, sg = u >> 6;
        int s0 = sg * 4;
        float xv[4];
#pragma unroll
        for (int i = 0; i < 4; i++)
            xv[i] = g_x[(size_t)(chunk_row + s0 + i) * DD + h*64 + p];
        uint2 hv, lv;
        split_pack2(xv[0], xv[1], hv.x, lv.x);
        split_pack2(xv[2], xv[3], hv.y, lv.y);
        uint32_t off = swz((uint32_t)(((p>>3) + (s0>>6)*8)*1024 + (p&7)*128 + (s0&63)*2));
        *(uint2*)(sm + FO_XHI + off) = hv;
        *(uint2*)(sm + FO_XLO + off) = lv;
    }
    // prev tile fill
    {
        int pbase = ((b * NCC + c) * HH + h) * 4096;
#pragma unroll
        for (int t = 0; t < 2; t++) {
            int u = tid + t * 512;
            int p = u >> 4, n4 = (u & 15) * 4;
            float4 v = *(const float4*)(g_prev + pbase + p*64 + n4);
            uint2 hv, lv;
            split_pack2(v.x, v.y, hv.x, lv.x);
            split_pack2(v.z, v.w, hv.y, lv.y);
            uint32_t off = swz((uint32_t)(p*128 + n4*2));
            *(uint2*)(sm + FO_PHI + off) = hv;
            *(uint2*)(sm + FO_PLO + off) = lv;
        }
    }
    FENCE_ASYNC();
    __syncthreads();

    if (wid == 0 && elect_one()) {
        MBAR_WAIT(sbase + 40, 0);
        uint64_t dCh = mk_desc(sbase + FO_CHI), dCl = mk_desc(sbase + FO_CLO);
        uint64_t dBh = mk_desc(sbase + FO_BHI), dBl = mk_desc(sbase + FO_BLO);
        uint32_t id1 = (SL == 128) ? IDESC_N(128) : IDESC_N(256);
#pragma unroll
        for (int ks = 0; ks < 4; ks++) {
            mma_f16_ss(tmem, dCh + ks*2, dBh + ks*2, id1, ks > 0);
            mma_f16_ss(tmem, dCh + ks*2, dBl + ks*2, id1, 1);
            mma_f16_ss(tmem, dCl + ks*2, dBh + ks*2, id1, 1);
        }
        TC_COMMIT(sbase + 8);
        uint64_t dPh = mk_desc(sbase + FO_PHI), dPl = mk_desc(sbase + FO_PLO);
        uint32_t id64 = IDESC_N(64);
#pragma unroll
        for (int ks = 0; ks < 4; ks++) {
            mma_f16_ss(tmem + 320, dCh + ks*2, dPh + ks*2, id64, ks > 0);
            mma_f16_ss(tmem + 320, dCh + ks*2, dPl + ks*2, id64, 1);
            mma_f16_ss(tmem + 320, dCl + ks*2, dPh + ks*2, id64, 1);
        }
        TC_COMMIT(sbase + 16);
    }
    MBAR_WAIT(sbase + 8, 0);
    TC_FENCE_AFTER();

    int sub = wid & 3, grp = wid >> 2;     // grp in 0..3 with 16 warps
    int lrow = sub * 32 + lid;
    float acl = acs[l0g + lrow];

    float erow[8];
#pragma unroll
    for (int j = 0; j < 8; j++) erow[j] = __expf(acl - acs[j * 32]);

    for (int sl = 0; sl < nsl; sl++) {
        if (sl == 1) MBAR_WAIT(sbase + 24, 0);
        {
            int rd = grp;                  // each warp group: one 32-col block
            uint32_t r[32];
            ldtm32(r, tmem + sl*128 + rd*32);
            TC_WAIT_LD();
            int colbase = sl*128 + rd*32;
            float er = erow[colbase >> 5];
#pragma unroll
            for (int j = 0; j < 32; j += 4) {
                float vv[4];
#pragma unroll
                for (int i = 0; i < 4; i++) {
                    int cg = colbase + j + i;
                    float v = __uint_as_float(r[j+i]) * er * ecol[cg];
                    vv[i] = (cg <= l0g + lrow) ? v : 0.f;
                }
                uint2 hv, lv;
                split_pack2(vv[0], vv[1], hv.x, lv.x);
                split_pack2(vv[2], vv[3], hv.y, lv.y);
                int sIn = rd*32 + j;
                uint32_t off = swz((uint32_t)(((lrow>>3) + (sIn>>6)*16)*1024
                                              + (lrow&7)*128 + (sIn&63)*2));
                *(uint2*)(sm + FO_BHI + off) = hv;
                *(uint2*)(sm + FO_BLO + off) = lv;
            }
        }
        FENCE_ASYNC();
        __syncthreads();
        if (wid == 0 && elect_one()) {
            uint64_t dSh = mk_desc(sbase + FO_BHI), dSl = mk_desc(sbase + FO_BLO);
            uint64_t dXh = mk_desc(sbase + FO_XHI), dXl = mk_desc(sbase + FO_XLO);
            uint32_t id64 = IDESC_N(64);
#pragma unroll
            for (int ks2 = 0; ks2 < 8; ks2++) {
                int ksg = sl*8 + ks2;
                uint64_t ao = (uint64_t)((ks2 >> 2)*1024 + (ks2 & 3)*2);
                uint64_t bo = (uint64_t)((ksg >> 2)*512 + (ksg & 3)*2);
                mma_f16_ss(tmem + 256, dSh + ao, dXh + bo, id64,
                           !(sl == 0 && ks2 == 0));
                mma_f16_ss(tmem + 256, dSh + ao, dXl + bo, id64, 1);
                mma_f16_ss(tmem + 256, dSl + ao, dXh + bo, id64, 1);
            }
            TC_COMMIT(sbase + 24 + (uint32_t)sl * 8);
        }
    }
    MBAR_WAIT(sbase + 24 + (uint32_t)(nsl - 1) * 8, 0);
    MBAR_WAIT(sbase + 16, 0);
    TC_FENCE_AFTER();

    if (grp < 2) {
        int row = chunk_row + l0g + lrow;
        uint32_t tile = (uint32_t)(row >> 7) * 16u + (uint32_t)h;
        char* dhi = yhi + ((size_t)tile << 14);
        char* dlo = ylo + ((size_t)tile << 14);
        float e = __expf(acl);
        uint32_t y1[32], y2[32];
        ldtm32(y1, tmem + 256 + grp*32);
        ldtm32(y2, tmem + 320 + grp*32);
        TC_WAIT_LD();
#pragma unroll
        for (int j = 0; j < 32; j += 4) {
            float vv[4];
#pragma unroll
            for (int i = 0; i < 4; i++)
                vv[i] = __uint_as_float(y1[j+i]) + e * __uint_as_float(y2[j+i]);
            uint2 hv, lv;
            split_pack2(vv[0], vv[1], hv.x, lv.x);
            split_pack2(vv[2], vv[3], hv.y, lv.y);
            uint32_t off = swz((uint32_t)((row & 127)*128 + (grp*32 + j)*2));
            *(uint2*)(dhi + off) = hv;
            *(uint2*)(dlo + off) = lv;
        }
        TC_FENCE_BEFORE();
    }
    __syncthreads();
    if (wid == 0) TC_DEALLOC(tmem, 512);
#else
    // CUDA-core fallback (512-safe: threads 256+ duplicate identical work)
    float* sC = (float*)(sm + FO_CHI);
    float* sS = (float*)(sm + FO_BHI);
    float* sB = (float*)(sm + FO_BLO);
    float* sX = (float*)(sm + FO_XHI);
    float* sP = (float*)(sm + FO_XLO);
    int tid2 = tid & 255;
    int tx = tid2 & 15, ty = tid2 >> 4;

    acs[tid2] = g_ac[(chunk_row + tid2) * HH + h];
    for (int t = 0; t < 16; t++) {
        int pr = tid2 + t * 256;
        int rr = pr >> 5, pp = pr & 31;
        int row = chunk_row + l0g + rr;
        sC[rr*64 + pp]      = ld_cb(tch, tcl, row, h, pp);
        sC[rr*64 + pp + 32] = ld_cb(tch, tcl, row, h, pp + 32);
    }
    {
        int pbase = ((b * NCC + c) * HH + h) * 4096;
        for (int t = 0; t < 16; t++) {
            int idx = tid2 + t * 256;
            sP[idx] = g_prev[pbase + idx];
        }
    }
    __syncthreads();

    float accD[8][4], accO[8][4];
#pragma unroll
    for (int i = 0; i < 8; i++)
#pragma unroll
        for (int j = 0; j < 4; j++) { accD[i][j] = 0.f; accO[i][j] = 0.f; }
    for (int n = 0; n < 64; n++)
#pragma unroll
        for (int i = 0; i < 8; i++)
#pragma unroll
            for (int j = 0; j < 4; j++)
                accO[i][j] += sC[(ty*8+i)*64 + n] * sP[(tx*4+j)*64 + n];

    for (int stile = 0; stile < SL/64; stile++) {
        for (int t = 0; t < 8; t++) {
            int pr = tid2 + t * 256;
            int rr = pr >> 5, pp = pr & 31;
            int row = chunk_row + stile*64 + rr;
            sB[rr*64 + pp]      = ld_cb(tbh, tbl, row, h, pp);
            sB[rr*64 + pp + 32] = ld_cb(tbh, tbl, row, h, pp + 32);
            const float* xx = g_x + (size_t)row * DD + h * 64;
            sX[rr*64 + pp]      = xx[pp];
            sX[rr*64 + pp + 32] = xx[pp + 32];
        }
        __syncthreads();
        for (int t = 0; t < 32; t++) {
            int idx = tid2 + t * 256;
            int l = idx >> 6, sIn = idx & 63;
            int sg = stile*64 + sIn;
            float v = 0.f;
            if (sg <= l0g + l) {
                for (int n = 0; n < 64; n++)
                    v += sC[l*64 + n] * sB[sIn*64 + n];
                v *= expf(acs[l0g + l] - acs[sg]);
            }
            sS[idx] = v;
        }
        __syncthreads();
        for (int s = 0; s < 64; s++)
#pragma unroll
            for (int i = 0; i < 8; i++)
#pragma unroll
                for (int j = 0; j < 4; j++)
                    accD[i][j] += sS[(ty*8+i)*64 + s] * sX[s*64 + tx*4 + j];
        __syncthreads();
    }
#pragma unroll
    for (int i = 0; i < 8; i++) {
        int lr = ty*8 + i;
        int row = chunk_row + l0g + lr;
        float e = expf(acs[l0g + lr]);
        uint32_t tile = (uint32_t)(row >> 7) * 16u + (uint32_t)h;
#pragma unroll
        for (int j = 0; j < 4; j++) {
            float v = accD[i][j] + e * accO[i][j];
            float hh, llv;
            split2(v, hh, llv);
            int col = tx*4 + j;
            uint32_t off = ((uint32_t)tile << 14) +
                           swz((uint32_t)((row & 127)*128 + col*2));
            *(__nv_bfloat16*)(yhi + off) = __float2bfloat16(hh);
            *(__nv_bfloat16*)(ylo + off) = __float2bfloat16(llv);
        }
    }
#endif
}

// ---------------------------------------------------------------------------
// kernel_launch
// ---------------------------------------------------------------------------
extern "C" void kernel_launch(void* const* d_in, const int* in_sizes, int n_in,
                              void* d_out, int out_size) {
    (void)in_sizes; (void)n_in; (void)out_size;
    const float* hs   = (const float*)d_in[0];
    const float* cosp = (const float*)d_in[1];
    const float* sinp = (const float*)d_in[2];
    const float* Wc   = (const float*)d_in[3];
    const float* Wb   = (const float*)d_in[4];
    const float* Wdt  = (const float*)d_in[5];
    const float* Wx   = (const float*)d_in[6];
    const float* Wout = (const float*)d_in[7];
    const float* A    = (const float*)d_in[8];
    float* out = (float*)d_out;
    float* fs  = out + (size_t)MM * DD;

    float *px;
    char *ahi, *alo, *whi, *wlo, *tch, *tcl, *tbh, *tbl;
    cudaGetSymbolAddress((void**)&px, g_x);
    cudaGetSymbolAddress((void**)&ahi, g_ahi);
    cudaGetSymbolAddress((void**)&alo, g_alo);
    cudaGetSymbolAddress((void**)&whi, g_wt_hi);
    cudaGetSymbolAddress((void**)&wlo, g_wt_lo);
    cudaGetSymbolAddress((void**)&tch, g_tc_hi);
    cudaGetSymbolAddress((void**)&tcl, g_tc_lo);
    cudaGetSymbolAddress((void**)&tbh, g_tb_hi);
    cudaGetSymbolAddress((void**)&tbl, g_tb_lo);

    int gemm_smem = 1024 + 2 * BUF_STRIDE;
    int prep_smem = 16 * 1028 * 4;
    cudaFuncSetAttribute(gemm3, cudaFuncAttributeMaxDynamicSharedMemorySize, gemm_smem);
    cudaFuncSetAttribute(gemm_t, cudaFuncAttributeMaxDynamicSharedMemorySize, gemm_smem);
    cudaFuncSetAttribute(prep, cudaFuncAttributeMaxDynamicSharedMemorySize, prep_smem);
    cudaFuncSetAttribute(flash_k, cudaFuncAttributeMaxDynamicSharedMemorySize, FL_SMEM);

    prep<<<PREP_FS + PREP_WS + PREP_DT, 256, prep_smem>>>(
        hs, Wc, Wb, Wx, Wout, Wdt, ahi, alo, whi, wlo);

    dim3 g3(12, MM / 128);
    gemm3<<<g3, 256, gemm_smem>>>(ahi, alo, whi, wlo, cosp, sinp,
                                  tch, tcl, tbh, tbl, px);

    kb_kernel<<<BB * NCC * HH, 256>>>(tbh, tbl, A);
    kc_kernel<<<BB * HH * 16, 256>>>(fs);

    flash_k<<<BB * NCC * HH * 2, 512, FL_SMEM>>>(tch, tcl, tbh, tbl, ahi, alo);

    dim3 gg(GN / 256, MM / 128);
    gemm_t<<<gg, 256, gemm_smem>>>(ahi, alo, whi + 3*WSZB, wlo + 3*WSZB, out);
}